// round 11
// baseline (speedup 1.0000x reference)
#include <cuda_runtime.h>
#include <cuda_bf16.h>
#include <cstdint>
#include <cstddef>

#define NATOM 100000
#define NCL   25000
#define EA    600000
#define EC    100000
#define EB    100000
#define HD    128
#define PD    256
#define BN_EPS 1e-5f
#define GAC   782
#define GCC   196

// ---------------- zeroed scratch arena (single memset) -----------------------------
#define Z_AGG_ATOM  0
#define Z_AGG_CL    12800000
#define Z_AGGM_C2A  16000000
#define Z_AGGM_A2C  28800000
#define Z_CNT_C2A   32000000
#define Z_CNT_A2C   32100000
#define Z_STATS_A   32125000
#define Z_STATS_C   32125512
#define Z_TOTAL     32126024
__device__ float g_zero[Z_TOTAL];

__device__ float g_pre_atom[(size_t)NATOM * PD];
__device__ float g_pre_cl[(size_t)NCL * PD];

#define OFF_GA 0
#define OFF_GC 32768
#define OFF_SA 65536
#define OFF_SC 131072
#define OFF_MA 196608
#define OFF_MC 229376
__device__ __nv_bfloat16 g_Bt_hi[262144];
__device__ __nv_bfloat16 g_Bt_lo[262144];

// ---------------- helpers ---------------------------------------------------------
__device__ __forceinline__ uint32_t smem_u32(const void* p) {
    uint32_t a;
    asm("{ .reg .u64 t; cvta.to.shared.u64 t, %1; cvt.u32.u64 %0, t; }" : "=r"(a) : "l"(p));
    return a;
}
__device__ __forceinline__ void ldm_x4(uint32_t* r, uint32_t addr) {
    asm volatile("ldmatrix.sync.aligned.m8n8.x4.shared.b16 {%0,%1,%2,%3}, [%4];"
                 : "=r"(r[0]), "=r"(r[1]), "=r"(r[2]), "=r"(r[3]) : "r"(addr));
}
__device__ __forceinline__ void mma16816(float* c, const uint32_t* a, const uint32_t* b) {
    asm volatile("mma.sync.aligned.m16n8k16.row.col.f32.bf16.bf16.f32 "
                 "{%0,%1,%2,%3}, {%4,%5,%6,%7}, {%8,%9}, {%0,%1,%2,%3};"
                 : "+f"(c[0]), "+f"(c[1]), "+f"(c[2]), "+f"(c[3])
                 : "r"(a[0]), "r"(a[1]), "r"(a[2]), "r"(a[3]), "r"(b[0]), "r"(b[1]));
}
__device__ __forceinline__ void red_v4(float* p, float a, float b, float c, float d) {
    asm volatile("red.global.add.v4.f32 [%0], {%1,%2,%3,%4};"
                 :: "l"(p), "f"(a), "f"(b), "f"(c), "f"(d) : "memory");
}
__device__ __forceinline__ void cp16(uint32_t s, const void* g) {
    asm volatile("cp.async.cg.shared.global [%0], [%1], 16;" :: "r"(s), "l"(g));
}
__device__ __forceinline__ uint32_t pack_lo_bf16(float lox, float loy) {
    uint32_t r;
    asm("cvt.rn.bf16x2.f32 %0, %1, %2;" : "=r"(r) : "f"(loy), "f"(lox));
    return r;
}
#define CP_COMMIT() asm volatile("cp.async.commit_group;" ::: "memory")
#define CP_WAIT0()  asm volatile("cp.async.wait_group 0;" ::: "memory")
#define CP_WAIT1()  asm volatile("cp.async.wait_group 1;" ::: "memory")

// split fp32 -> (hi uint2 pair, lo uint2 pair) for a float4
__device__ __forceinline__ void split4(float4 v, uint2& hp, uint2& lp) {
    uint32_t bx = __float_as_uint(v.x), by = __float_as_uint(v.y);
    uint32_t bz = __float_as_uint(v.z), bw = __float_as_uint(v.w);
    hp.x = __byte_perm(bx, by, 0x7632);
    hp.y = __byte_perm(bz, bw, 0x7632);
    lp.x = pack_lo_bf16(v.x - __uint_as_float(bx & 0xFFFF0000u),
                        v.y - __uint_as_float(by & 0xFFFF0000u));
    lp.y = pack_lo_bf16(v.z - __uint_as_float(bz & 0xFFFF0000u),
                        v.w - __uint_as_float(bw & 0xFFFF0000u));
}

// ---------------- mega scatter + wsplit (one launch, unchanged) --------------------
__constant__ int c_ws_N[8]     = {256, 256, 256, 256, 256, 256, 128, 128};
__constant__ int c_ws_koff[8]  = {0, 0, 0, 128, 0, 128, 0, 0};
__constant__ int c_ws_kout[8]  = {128, 128, 256, 256, 256, 256, 256, 256};
__constant__ int c_ws_doff[8]  = {OFF_GA, OFF_GC, OFF_SA, OFF_SA, OFF_SC, OFF_SC, OFF_MA, OFF_MC};

struct MegaArgs {
    const float *x, *ea, *xcl, *cea;
    const int *ei_a, *ei_c, *ei_a2c, *ei_c2a;
    float *agg_atom, *agg_cl, *aggm_a2c, *cnt_a2c, *aggm_c2a, *cnt_c2a;
    const float* wsrc[8];
    __nv_bfloat16 *oh, *ol;
};

#define SCATTER_BLOCKS 100000
#define WSPLIT_BLOCKS  1024

__global__ void mega_scatter(MegaArgs A) {
    int b = blockIdx.x;
    if (b >= SCATTER_BLOCKS) {
        int i = (b - SCATTER_BLOCKS) * 256 + threadIdx.x;
        int seg = i >> 15;
        int w = i & 32767;
        int N = c_ws_N[seg];
        int k = w / N, n = w - k * N;
        float v = A.wsrc[seg][w];
        uint32_t bits = __float_as_uint(v);
        uint32_t hbits = bits & 0xFFFF0000u;
        float lo = v - __uint_as_float(hbits);
        size_t o = (size_t)n * c_ws_kout[seg] + c_ws_koff[seg] + k + c_ws_doff[seg];
        A.oh[o] = __ushort_as_bfloat16((unsigned short)(hbits >> 16));
        A.ol[o] = __float2bfloat16(lo);
        return;
    }
    int w = b * 8 + (threadIdx.x >> 5);
    int lane = threadIdx.x & 31;
    if (w < 600000) {
        int e = w;
        int src = A.ei_a[e];
        int dst = A.ei_a[EA + e];
        float4 xv = reinterpret_cast<const float4*>(A.x + (size_t)src * HD)[lane];
        float4 ev = reinterpret_cast<const float4*>(A.ea + (size_t)e * HD)[lane];
        red_v4(A.agg_atom + (size_t)dst * HD + lane * 4,
               fmaxf(xv.x + ev.x, 0.0f), fmaxf(xv.y + ev.y, 0.0f),
               fmaxf(xv.z + ev.z, 0.0f), fmaxf(xv.w + ev.w, 0.0f));
    } else if (w < 700000) {
        int e = w - 600000;
        int src = A.ei_c[e];
        int dst = A.ei_c[EC + e];
        float4 xv = reinterpret_cast<const float4*>(A.xcl + (size_t)src * HD)[lane];
        float4 ev = reinterpret_cast<const float4*>(A.cea + (size_t)e * HD)[lane];
        red_v4(A.agg_cl + (size_t)dst * HD + lane * 4,
               fmaxf(xv.x + ev.x, 0.0f), fmaxf(xv.y + ev.y, 0.0f),
               fmaxf(xv.z + ev.z, 0.0f), fmaxf(xv.w + ev.w, 0.0f));
    } else if (w < 750000) {
        int e0 = (w - 700000) * 2, e1 = e0 + 1;
        int s0 = A.ei_a2c[e0], s1 = A.ei_a2c[e1];
        int d0 = A.ei_a2c[EB + e0], d1 = A.ei_a2c[EB + e1];
        float4 v0 = reinterpret_cast<const float4*>(A.x + (size_t)s0 * HD)[lane];
        float4 v1 = reinterpret_cast<const float4*>(A.x + (size_t)s1 * HD)[lane];
        red_v4(A.aggm_a2c + (size_t)d0 * HD + lane * 4, v0.x, v0.y, v0.z, v0.w);
        red_v4(A.aggm_a2c + (size_t)d1 * HD + lane * 4, v1.x, v1.y, v1.z, v1.w);
        if (lane == 0) {
            atomicAdd(&A.cnt_a2c[d0], 1.0f);
            atomicAdd(&A.cnt_a2c[d1], 1.0f);
        }
    } else {
        int e0 = (w - 750000) * 2, e1 = e0 + 1;
        int s0 = A.ei_c2a[e0], s1 = A.ei_c2a[e1];
        int d0 = A.ei_c2a[EB + e0], d1 = A.ei_c2a[EB + e1];
        float4 v0 = reinterpret_cast<const float4*>(A.xcl + (size_t)s0 * HD)[lane];
        float4 v1 = reinterpret_cast<const float4*>(A.xcl + (size_t)s1 * HD)[lane];
        red_v4(A.aggm_c2a + (size_t)d0 * HD + lane * 4, v0.x, v0.y, v0.z, v0.w);
        red_v4(A.aggm_c2a + (size_t)d1 * HD + lane * 4, v1.x, v1.y, v1.z, v1.w);
        if (lane == 0) {
            atomicAdd(&A.cnt_c2a[d0], 1.0f);
            atomicAdd(&A.cnt_c2a[d1], 1.0f);
        }
    }
}

// ================== GINE GEMM pair, k=64 double-buffered pipeline ==================
// smem: bias @0 (1KB); A bufs @1024 (2 x 32KB: hi16+lo16); B bufs @66560 (2 x 64KB: hi32+lo32)
#define G_A   1024
#define G_B   66560
#define SMEM_GINE 197632

struct GineP {
    const float *A0, *A1;
    const __nv_bfloat16 *bh, *bl;
    const float *bias, *eps;
    float *stats, *C;
    int M;
};

__global__ __launch_bounds__(512)
void gine_gemm_pair(GineP Pa, GineP Pc) {
    const bool isA = blockIdx.x < GAC;
    const GineP P = isA ? Pa : Pc;
    const int m0 = (isA ? blockIdx.x : blockIdx.x - GAC) * 128;

    extern __shared__ char smem[];
    uint32_t sb = smem_u32(smem);
    const int tid = threadIdx.x;
    const int wid = tid >> 5;
    const int lid = tid & 31;
    const int wm = wid & 3;
    const int wn = wid >> 2;

    float* bias_s = reinterpret_cast<float*>(smem);
    if (tid < 256) bias_s[tid] = P.bias[tid];

    const float ef = 1.0f + *P.eps;

    float acc[2][8][4];
#pragma unroll
    for (int mt = 0; mt < 2; mt++)
#pragma unroll
        for (int nt = 0; nt < 8; nt++)
#pragma unroll
            for (int j = 0; j < 4; j++) acc[mt][nt][j] = 0.0f;

    const int arow = wm * 32 + (lid & 15);
    const int akp = lid >> 4;
    const int bn = wn * 64 + (lid & 7) + ((lid >> 4) << 3);
    const int bkp = (lid >> 3) & 1;

    // ---- producers ----
    auto loadB = [&](int c, int b) {
#pragma unroll
        for (int it = 0; it < 4; it++) {
            int idx = tid + it * 512;          // 0..2047
            int n = idx >> 3;
            int ch = idx & 7;
            uint32_t off = n * 128 + ((ch ^ (n & 7)) << 4);
            cp16(sb + G_B + b * 65536 + off, P.bh + (size_t)n * 128 + c * 64 + ch * 8);
            cp16(sb + G_B + b * 65536 + 32768 + off, P.bl + (size_t)n * 128 + c * 64 + ch * 8);
        }
        CP_COMMIT();
    };
    auto prodA = [&](int c, int b) {
#pragma unroll
        for (int it = 0; it < 4; it++) {
            int idx = tid + it * 512;          // 0..2047 float4
            int r = idx >> 4;
            int c4 = (idx & 15) * 4;
            int gr = m0 + r;
            int gk = c * 64 + c4;
            float4 v = make_float4(0.f, 0.f, 0.f, 0.f);
            if (gr < P.M) {
                float4 a = *reinterpret_cast<const float4*>(P.A0 + (size_t)gr * 128 + gk);
                float4 g = *reinterpret_cast<const float4*>(P.A1 + (size_t)gr * 128 + gk);
                v.x = fmaf(ef, a.x, g.x); v.y = fmaf(ef, a.y, g.y);
                v.z = fmaf(ef, a.z, g.z); v.w = fmaf(ef, a.w, g.w);
            }
            uint2 hp, lp;
            split4(v, hp, lp);
            uint32_t off = r * 128 + (((c4 >> 3) ^ (r & 7)) << 4) + ((c4 & 4) << 1);
            *reinterpret_cast<uint2*>(smem + G_A + b * 32768 + off) = hp;
            *reinterpret_cast<uint2*>(smem + G_A + b * 32768 + 16384 + off) = lp;
        }
    };
    auto mmaC = [&](int b) {
        uint32_t abase = sb + G_A + b * 32768;
        uint32_t bbase = sb + G_B + b * 65536;
#pragma unroll
        for (int ks = 0; ks < 4; ks++) {
            uint32_t ah[2][4], al[2][4];
#pragma unroll
            for (int mt = 0; mt < 2; mt++) {
                int r = arow + mt * 16;
                uint32_t ch = (uint32_t)((ks * 2 + akp) ^ (r & 7));
                uint32_t off = r * 128 + (ch << 4);
                ldm_x4(ah[mt], abase + off);
                ldm_x4(al[mt], abase + 16384 + off);
            }
#pragma unroll
            for (int np = 0; np < 4; np++) {
                int n = bn + np * 16;
                uint32_t ch = (uint32_t)((ks * 2 + bkp) ^ (n & 7));
                uint32_t off = n * 128 + (ch << 4);
                uint32_t bh[4], bl[4];
                ldm_x4(bh, bbase + off);
                ldm_x4(bl, bbase + 32768 + off);
#pragma unroll
                for (int mt = 0; mt < 2; mt++) {
#pragma unroll
                    for (int sn = 0; sn < 2; sn++) {
                        float* c = acc[mt][np * 2 + sn];
                        mma16816(c, ah[mt], bh + sn * 2);
                        mma16816(c, ah[mt], bl + sn * 2);
                        mma16816(c, al[mt], bh + sn * 2);
                    }
                }
            }
        }
    };

    // ---- pipeline: 2 chunks of k=64 ----
    loadB(0, 0);
    prodA(0, 0);
    CP_WAIT0();
    __syncthreads();
#pragma unroll
    for (int c = 0; c < 2; c++) {
        int cb = c & 1;
        if (c < 1) loadB(c + 1, 1 - cb);
        mmaC(cb);
        if (c < 1) prodA(c + 1, 1 - cb);
        if (c < 1) CP_WAIT0();
        __syncthreads();
    }

    // ---- epilogue + fused column stats ----
    const int g = lid >> 2;
    const int tig = lid & 3;
#pragma unroll
    for (int nt = 0; nt < 8; nt++) {
        int nl = wn * 64 + nt * 8 + 2 * tig;
        float b0 = bias_s[nl], b1 = bias_s[nl + 1];
        float s0 = 0.f, s1 = 0.f, q0 = 0.f, q1 = 0.f;
#pragma unroll
        for (int mt = 0; mt < 2; mt++) {
            int m = m0 + wm * 32 + mt * 16 + g;
            if (m < P.M) {
                float ox = acc[mt][nt][0] + b0, oy = acc[mt][nt][1] + b1;
                *reinterpret_cast<float2*>(P.C + (size_t)m * PD + nl) = make_float2(ox, oy);
                s0 += ox; s1 += oy; q0 += ox * ox; q1 += oy * oy;
            }
            if (m + 8 < P.M) {
                float ox = acc[mt][nt][2] + b0, oy = acc[mt][nt][3] + b1;
                *reinterpret_cast<float2*>(P.C + (size_t)(m + 8) * PD + nl) = make_float2(ox, oy);
                s0 += ox; s1 += oy; q0 += ox * ox; q1 += oy * oy;
            }
        }
#pragma unroll
        for (int d = 4; d < 32; d <<= 1) {
            s0 += __shfl_xor_sync(0xFFFFFFFFu, s0, d);
            s1 += __shfl_xor_sync(0xFFFFFFFFu, s1, d);
            q0 += __shfl_xor_sync(0xFFFFFFFFu, q0, d);
            q1 += __shfl_xor_sync(0xFFFFFFFFu, q1, d);
        }
        if (g == 0) {
            atomicAdd(P.stats + nl, s0);
            atomicAdd(P.stats + nl + 1, s1);
            atomicAdd(P.stats + PD + nl, q0);
            atomicAdd(P.stats + PD + nl + 1, q1);
        }
    }
}

// ================== fused SAGE + MERGE, pipelined ==================
// smem: bias1 @0(1K), bias2 @1024(512), scale @1536(1K), shift @2560(1K)
//       A1 bufs @4096  (2 x 32KB: hi16+lo16)
//       B1 bufs @69632 (2 x 64KB: hi32+lo32)
//       A2 (phase>=2) @69632: hi 64KB, lo @135168 64KB   (reuses B1)
//       B2 bufs (phase 3) @4096 (2 x 32KB: hi16+lo16)    (reuses A1)
#define F_BIAS1 0
#define F_BIAS2 1024
#define F_SCALE 1536
#define F_SHIFT 2560
#define F_A1    4096
#define F_B1    69632
#define F_A2H   69632
#define F_A2L   135168
#define F_B2    4096
#define SMEM_FUSED 200704

struct FusedP {
    const float *aggm, *xdst, *cnt;
    const __nv_bfloat16 *b1h, *b1l;
    const float *sbl, *sbr, *pre;
    const float *stats, *gamma, *beta;
    const __nv_bfloat16 *b2h, *b2l;
    const float *mbias;
    float *C;
    int M;
    float invM;
};

__global__ __launch_bounds__(512)
void sage_merge_pair(FusedP Pa, FusedP Pc) {
    const bool isA = blockIdx.x < GAC;
    const FusedP P = isA ? Pa : Pc;
    const int m0 = (isA ? blockIdx.x : blockIdx.x - GAC) * 128;

    extern __shared__ char smem[];
    uint32_t sb = smem_u32(smem);
    const int tid = threadIdx.x;
    const int wid = tid >> 5;
    const int lid = tid & 31;

    float* bias1_s = reinterpret_cast<float*>(smem + F_BIAS1);
    float* bias2_s = reinterpret_cast<float*>(smem + F_BIAS2);
    float* scale_s = reinterpret_cast<float*>(smem + F_SCALE);
    float* shift_s = reinterpret_cast<float*>(smem + F_SHIFT);
    if (tid < 256) {
        bias1_s[tid] = P.sbl[tid] + P.sbr[tid];
        // inline BN finalize
        float mu = P.stats[tid] * P.invM;
        float var = P.stats[PD + tid] * P.invM - mu * mu;
        float s = P.gamma[tid] * rsqrtf(var + BN_EPS);
        scale_s[tid] = s;
        shift_s[tid] = P.beta[tid] - mu * s;
    } else if (tid < 384) {
        bias2_s[tid - 256] = P.mbias[tid - 256];
    }

    // ===== Phase 1: SAGE GEMM (K=256), 4 chunks of k=64, double-buffered =====
    const int wm = wid & 3;
    const int wn = wid >> 2;
    float acc[2][8][4];
#pragma unroll
    for (int mt = 0; mt < 2; mt++)
#pragma unroll
        for (int nt = 0; nt < 8; nt++)
#pragma unroll
            for (int j = 0; j < 4; j++) acc[mt][nt][j] = 0.0f;

    const int arow = wm * 32 + (lid & 15);
    const int akp = lid >> 4;
    const int bn = wn * 64 + (lid & 7) + ((lid >> 4) << 3);
    const int bkp = (lid >> 3) & 1;

    auto loadB1 = [&](int c, int b) {
#pragma unroll
        for (int it = 0; it < 4; it++) {
            int idx = tid + it * 512;          // 0..2047
            int n = idx >> 3;
            int ch = idx & 7;
            uint32_t off = n * 128 + ((ch ^ (n & 7)) << 4);
            cp16(sb + F_B1 + b * 65536 + off, P.b1h + (size_t)n * 256 + c * 64 + ch * 8);
            cp16(sb + F_B1 + b * 65536 + 32768 + off, P.b1l + (size_t)n * 256 + c * 64 + ch * 8);
        }
        CP_COMMIT();
    };
    auto prodA1 = [&](int c, int b) {
#pragma unroll
        for (int it = 0; it < 4; it++) {
            int idx = tid + it * 512;          // 0..2047 float4
            int r = idx >> 4;
            int c4 = (idx & 15) * 4;
            int gr = m0 + r;
            int gk = c * 64 + c4;
            float4 v = make_float4(0.f, 0.f, 0.f, 0.f);
            if (gr < P.M) {
                if (gk < 128) {
                    float4 a = *reinterpret_cast<const float4*>(P.aggm + (size_t)gr * 128 + gk);
                    float inv = __frcp_rn(fmaxf(P.cnt[gr], 1.0f));
                    v.x = a.x * inv; v.y = a.y * inv; v.z = a.z * inv; v.w = a.w * inv;
                } else {
                    v = *reinterpret_cast<const float4*>(P.xdst + (size_t)gr * 128 + (gk - 128));
                }
            }
            uint2 hp, lp;
            split4(v, hp, lp);
            uint32_t off = r * 128 + (((c4 >> 3) ^ (r & 7)) << 4) + ((c4 & 4) << 1);
            *reinterpret_cast<uint2*>(smem + F_A1 + b * 32768 + off) = hp;
            *reinterpret_cast<uint2*>(smem + F_A1 + b * 32768 + 16384 + off) = lp;
        }
    };
    auto mma1 = [&](int b) {
        uint32_t abase = sb + F_A1 + b * 32768;
        uint32_t bbase = sb + F_B1 + b * 65536;
#pragma unroll
        for (int ks = 0; ks < 4; ks++) {
            uint32_t ah[2][4], al[2][4];
#pragma unroll
            for (int mt = 0; mt < 2; mt++) {
                int r = arow + mt * 16;
                uint32_t ch = (uint32_t)((ks * 2 + akp) ^ (r & 7));
                uint32_t off = r * 128 + (ch << 4);
                ldm_x4(ah[mt], abase + off);
                ldm_x4(al[mt], abase + 16384 + off);
            }
#pragma unroll
            for (int np = 0; np < 4; np++) {
                int n = bn + np * 16;
                uint32_t ch = (uint32_t)((ks * 2 + bkp) ^ (n & 7));
                uint32_t off = n * 128 + (ch << 4);
                uint32_t bh[4], bl[4];
                ldm_x4(bh, bbase + off);
                ldm_x4(bl, bbase + 32768 + off);
#pragma unroll
                for (int mt = 0; mt < 2; mt++) {
#pragma unroll
                    for (int sn = 0; sn < 2; sn++) {
                        float* c = acc[mt][np * 2 + sn];
                        mma16816(c, ah[mt], bh + sn * 2);
                        mma16816(c, ah[mt], bl + sn * 2);
                        mma16816(c, al[mt], bh + sn * 2);
                    }
                }
            }
        }
    };

    loadB1(0, 0);
    prodA1(0, 0);
    CP_WAIT0();
    __syncthreads();
#pragma unroll
    for (int c = 0; c < 4; c++) {
        int cb = c & 1;
        if (c < 3) loadB1(c + 1, 1 - cb);
        mma1(cb);
        if (c < 3) prodA1(c + 1, 1 - cb);
        if (c < 3) CP_WAIT0();
        __syncthreads();
    }

    // ===== B2 prefetch (chunks 0,1 of 4) into freed A1 region =====
    auto loadB2 = [&](int c, int b) {
#pragma unroll
        for (int it = 0; it < 2; it++) {
            int idx = tid + it * 512;          // 0..1023
            int n = idx >> 3;
            int ch = idx & 7;
            uint32_t off = n * 128 + ((ch ^ (n & 7)) << 4);
            cp16(sb + F_B2 + b * 32768 + off, P.b2h + (size_t)n * 256 + c * 64 + ch * 8);
            cp16(sb + F_B2 + b * 32768 + 16384 + off, P.b2l + (size_t)n * 256 + c * 64 + ch * 8);
        }
        CP_COMMIT();
    };
    loadB2(0, 0);
    loadB2(1, 1);

    // ===== Phase 2: A2 = relu(pre*scale+shift) + S + bias -> smem split bf16 =====
    {
        const int g = lid >> 2;
        const int tig = lid & 3;
#pragma unroll
        for (int nt = 0; nt < 8; nt++) {
            int nl = wn * 64 + nt * 8 + 2 * tig;
            float b0 = bias1_s[nl], b1 = bias1_s[nl + 1];
            float sc0 = scale_s[nl], sc1 = scale_s[nl + 1];
            float sh0 = shift_s[nl], sh1 = shift_s[nl + 1];
#pragma unroll
            for (int mt = 0; mt < 2; mt++) {
#pragma unroll
                for (int half = 0; half < 2; half++) {
                    int r = wm * 32 + mt * 16 + g + half * 8;
                    int m = m0 + r;
                    float ax = 0.f, ay = 0.f;
                    if (m < P.M) {
                        float2 p = *reinterpret_cast<const float2*>(P.pre + (size_t)m * PD + nl);
                        ax = fmaxf(fmaf(p.x, sc0, sh0), 0.f) + acc[mt][nt][half * 2 + 0] + b0;
                        ay = fmaxf(fmaf(p.y, sc1, sh1), 0.f) + acc[mt][nt][half * 2 + 1] + b1;
                    }
                    uint32_t bx = __float_as_uint(ax), by = __float_as_uint(ay);
                    uint32_t hp = __byte_perm(bx, by, 0x7632);
                    uint32_t lp = pack_lo_bf16(ax - __uint_as_float(bx & 0xFFFF0000u),
                                               ay - __uint_as_float(by & 0xFFFF0000u));
                    uint32_t off = r * 512 + (((nl >> 3) ^ (r & 7)) << 4) + (nl & 7) * 2;
                    *reinterpret_cast<uint32_t*>(smem + F_A2H + off) = hp;
                    *reinterpret_cast<uint32_t*>(smem + F_A2L + off) = lp;
                }
            }
        }
    }
    __syncthreads();

    // ===== Phase 3: merge GEMM from smem A2, 4 chunks of k=64, double-buffered =====
    const int wm2 = wid & 7;
    const int wn2 = wid >> 3;
    float acc2[8][4];
#pragma unroll
    for (int nt = 0; nt < 8; nt++)
#pragma unroll
        for (int j = 0; j < 4; j++) acc2[nt][j] = 0.0f;

    const int arow2 = wm2 * 16 + (lid & 15);
    const int akp2 = lid >> 4;
    const int bn2 = wn2 * 64 + (lid & 7) + ((lid >> 4) << 3);
    const int bkp2 = (lid >> 3) & 1;

    auto mma2 = [&](int c, int b) {
        uint32_t bbase = sb + F_B2 + b * 32768;
#pragma unroll
        for (int ks = 0; ks < 4; ks++) {
            uint32_t ah[4], al[4];
            {
                int r = arow2;
                uint32_t ch = (uint32_t)((c * 8 + ks * 2 + akp2) ^ (r & 7));
                uint32_t off = r * 512 + (ch << 4);
                ldm_x4(ah, sb + F_A2H + off);
                ldm_x4(al, sb + F_A2L + off);
            }
#pragma unroll
            for (int np = 0; np < 4; np++) {
                int n = bn2 + np * 16;
                uint32_t ch = (uint32_t)((ks * 2 + bkp2) ^ (n & 7));
                uint32_t off = n * 128 + (ch << 4);
                uint32_t bh[4], bl[4];
                ldm_x4(bh, bbase + off);
                ldm_x4(bl, bbase + 16384 + off);
#pragma unroll
                for (int sn = 0; sn < 2; sn++) {
                    float* cc = acc2[np * 2 + sn];
                    mma16816(cc, ah, bh + sn * 2);
                    mma16816(cc, ah, bl + sn * 2);
                    mma16816(cc, al, bh + sn * 2);
                }
            }
        }
    };

#pragma unroll
    for (int c = 0; c < 4; c++) {
        if (c == 3) CP_WAIT0(); else CP_WAIT1();
        __syncthreads();
        mma2(c, c & 1);
        __syncthreads();
        if (c < 2) loadB2(c + 2, c & 1);
    }

    // ===== epilogue =====
    {
        const int g = lid >> 2;
        const int tig = lid & 3;
#pragma unroll
        for (int nt = 0; nt < 8; nt++) {
            int nl = wn2 * 64 + nt * 8 + 2 * tig;
            float b0 = bias2_s[nl], b1 = bias2_s[nl + 1];
            int m = m0 + wm2 * 16 + g;
            if (m < P.M) {
                *reinterpret_cast<float2*>(P.C + (size_t)m * HD + nl) =
                    make_float2(acc2[nt][0] + b0, acc2[nt][1] + b1);
            }
            if (m + 8 < P.M) {
                *reinterpret_cast<float2*>(P.C + (size_t)(m + 8) * HD + nl) =
                    make_float2(acc2[nt][2] + b0, acc2[nt][3] + b1);
            }
        }
    }
}

// -----------------------------------------------------------------------------------
extern "C" void kernel_launch(void* const* d_in, const int* in_sizes, int n_in,
                              void* d_out, int out_size) {
    const float* x         = (const float*)d_in[0];
    const float* edge_attr = (const float*)d_in[1];
    const float* x_cl      = (const float*)d_in[2];
    const float* c2c_ea    = (const float*)d_in[3];

    int pbase, ebase;
    if (in_sizes[4] == 2 * EA) { ebase = 4; pbase = 8; }
    else                       { pbase = 4; ebase = 26; }

    const int* ei_a   = (const int*)d_in[ebase + 0];
    const int* ei_c2c = (const int*)d_in[ebase + 1];
    const int* ei_a2c = (const int*)d_in[ebase + 2];
    const int* ei_c2a = (const int*)d_in[ebase + 3];

    const float* atom_eps   = (const float*)d_in[pbase + 0];
    const float* atom_W     = (const float*)d_in[pbase + 1];
    const float* atom_b     = (const float*)d_in[pbase + 2];
    const float* atom_gamma = (const float*)d_in[pbase + 3];
    const float* atom_beta  = (const float*)d_in[pbase + 4];
    const float* cl_eps     = (const float*)d_in[pbase + 5];
    const float* cl_W       = (const float*)d_in[pbase + 6];
    const float* cl_b       = (const float*)d_in[pbase + 7];
    const float* cl_gamma   = (const float*)d_in[pbase + 8];
    const float* cl_beta    = (const float*)d_in[pbase + 9];
    const float* a2c_Wl     = (const float*)d_in[pbase + 10];
    const float* a2c_bl     = (const float*)d_in[pbase + 11];
    const float* a2c_Wr     = (const float*)d_in[pbase + 12];
    const float* a2c_br     = (const float*)d_in[pbase + 13];
    const float* c2a_Wl     = (const float*)d_in[pbase + 14];
    const float* c2a_bl     = (const float*)d_in[pbase + 15];
    const float* c2a_Wr     = (const float*)d_in[pbase + 16];
    const float* c2a_br     = (const float*)d_in[pbase + 17];
    const float* merge_atom_W = (const float*)d_in[pbase + 18];
    const float* merge_atom_b = (const float*)d_in[pbase + 19];
    const float* merge_cl_W   = (const float*)d_in[pbase + 20];
    const float* merge_cl_b   = (const float*)d_in[pbase + 21];

    float* out = (float*)d_out;

    float *p_zero, *p_pre_atom, *p_pre_cl;
    __nv_bfloat16 *p_Bt_hi, *p_Bt_lo;
    cudaGetSymbolAddress((void**)&p_zero, g_zero);
    cudaGetSymbolAddress((void**)&p_pre_atom, g_pre_atom);
    cudaGetSymbolAddress((void**)&p_pre_cl, g_pre_cl);
    cudaGetSymbolAddress((void**)&p_Bt_hi, g_Bt_hi);
    cudaGetSymbolAddress((void**)&p_Bt_lo, g_Bt_lo);

    float* p_agg_atom   = p_zero + Z_AGG_ATOM;
    float* p_agg_cl     = p_zero + Z_AGG_CL;
    float* p_aggm_c2a   = p_zero + Z_AGGM_C2A;
    float* p_aggm_a2c   = p_zero + Z_AGGM_A2C;
    float* p_cnt_c2a    = p_zero + Z_CNT_C2A;
    float* p_cnt_a2c    = p_zero + Z_CNT_A2C;
    float* p_stats_atom = p_zero + Z_STATS_A;
    float* p_stats_cl   = p_zero + Z_STATS_C;

    cudaMemsetAsync(p_zero, 0, (size_t)Z_TOTAL * 4, 0);

    cudaFuncSetAttribute((const void*)gine_gemm_pair,
                         cudaFuncAttributeMaxDynamicSharedMemorySize, SMEM_GINE);
    cudaFuncSetAttribute((const void*)sage_merge_pair,
                         cudaFuncAttributeMaxDynamicSharedMemorySize, SMEM_FUSED);

    // ---- mega scatter + wsplit ----
    {
        MegaArgs A;
        A.x = x; A.ea = edge_attr; A.xcl = x_cl; A.cea = c2c_ea;
        A.ei_a = ei_a; A.ei_c = ei_c2c; A.ei_a2c = ei_a2c; A.ei_c2a = ei_c2a;
        A.agg_atom = p_agg_atom; A.agg_cl = p_agg_cl;
        A.aggm_a2c = p_aggm_a2c; A.cnt_a2c = p_cnt_a2c;
        A.aggm_c2a = p_aggm_c2a; A.cnt_c2a = p_cnt_c2a;
        A.wsrc[0] = atom_W;  A.wsrc[1] = cl_W;
        A.wsrc[2] = c2a_Wl;  A.wsrc[3] = c2a_Wr;
        A.wsrc[4] = a2c_Wl;  A.wsrc[5] = a2c_Wr;
        A.wsrc[6] = merge_atom_W; A.wsrc[7] = merge_cl_W;
        A.oh = p_Bt_hi; A.ol = p_Bt_lo;
        mega_scatter<<<SCATTER_BLOCKS + WSPLIT_BLOCKS, 256>>>(A);
    }

    // ---- GINE GEMM pair ----
    {
        GineP Pa{x, p_agg_atom, p_Bt_hi + OFF_GA, p_Bt_lo + OFF_GA,
                 atom_b, atom_eps, p_stats_atom, p_pre_atom, NATOM};
        GineP Pc{x_cl, p_agg_cl, p_Bt_hi + OFF_GC, p_Bt_lo + OFF_GC,
                 cl_b, cl_eps, p_stats_cl, p_pre_cl, NCL};
        gine_gemm_pair<<<GAC + GCC, 512, SMEM_GINE>>>(Pa, Pc);
    }

    // ---- fused SAGE + MERGE pair (BN finalize inlined) ----
    {
        FusedP Pa{p_aggm_c2a, x, p_cnt_c2a,
                  p_Bt_hi + OFF_SA, p_Bt_lo + OFF_SA, c2a_bl, c2a_br,
                  p_pre_atom, p_stats_atom, atom_gamma, atom_beta,
                  p_Bt_hi + OFF_MA, p_Bt_lo + OFF_MA, merge_atom_b, out,
                  NATOM, 1.0f / NATOM};
        FusedP Pc{p_aggm_a2c, x_cl, p_cnt_a2c,
                  p_Bt_hi + OFF_SC, p_Bt_lo + OFF_SC, a2c_bl, a2c_br,
                  p_pre_cl, p_stats_cl, cl_gamma, cl_beta,
                  p_Bt_hi + OFF_MC, p_Bt_lo + OFF_MC, merge_cl_b,
                  out + (size_t)NATOM * HD,
                  NCL, 1.0f / NCL};
        sage_merge_pair<<<GAC + GCC, 512, SMEM_FUSED>>>(Pa, Pc);
    }
}

// round 13
// speedup vs baseline: 1.0664x; 1.0664x over previous
#include <cuda_runtime.h>
#include <cuda_bf16.h>
#include <cstdint>
#include <cstddef>

#define NATOM 100000
#define NCL   25000
#define EA    600000
#define EC    100000
#define EB    100000
#define HD    128
#define PD    256
#define BN_EPS 1e-5f
#define GAC   782
#define GCC   196

// ---------------- zeroed scratch arena (single memset) -----------------------------
#define Z_AGG_ATOM  0
#define Z_AGG_CL    12800000
#define Z_AGGM_C2A  16000000
#define Z_AGGM_A2C  28800000
#define Z_CNT_C2A   32000000
#define Z_CNT_A2C   32100000
#define Z_STATS_A   32125000
#define Z_STATS_C   32125512
#define Z_TOTAL     32126024
__device__ float g_zero[Z_TOTAL];

__device__ float g_pre_atom[(size_t)NATOM * PD];
__device__ float g_pre_cl[(size_t)NCL * PD];
__device__ float g_scale_atom[PD];
__device__ float g_shift_atom[PD];
__device__ float g_scale_cl[PD];
__device__ float g_shift_cl[PD];

#define OFF_GA 0
#define OFF_GC 32768
#define OFF_SA 65536
#define OFF_SC 131072
#define OFF_MA 196608
#define OFF_MC 229376
__device__ __nv_bfloat16 g_Bt_hi[262144];
__device__ __nv_bfloat16 g_Bt_lo[262144];

// ---------------- helpers ---------------------------------------------------------
__device__ __forceinline__ uint32_t smem_u32(const void* p) {
    uint32_t a;
    asm("{ .reg .u64 t; cvta.to.shared.u64 t, %1; cvt.u32.u64 %0, t; }" : "=r"(a) : "l"(p));
    return a;
}
__device__ __forceinline__ void ldm_x4(uint32_t* r, uint32_t addr) {
    asm volatile("ldmatrix.sync.aligned.m8n8.x4.shared.b16 {%0,%1,%2,%3}, [%4];"
                 : "=r"(r[0]), "=r"(r[1]), "=r"(r[2]), "=r"(r[3]) : "r"(addr));
}
__device__ __forceinline__ void mma16816(float* c, const uint32_t* a, const uint32_t* b) {
    asm volatile("mma.sync.aligned.m16n8k16.row.col.f32.bf16.bf16.f32 "
                 "{%0,%1,%2,%3}, {%4,%5,%6,%7}, {%8,%9}, {%0,%1,%2,%3};"
                 : "+f"(c[0]), "+f"(c[1]), "+f"(c[2]), "+f"(c[3])
                 : "r"(a[0]), "r"(a[1]), "r"(a[2]), "r"(a[3]), "r"(b[0]), "r"(b[1]));
}
__device__ __forceinline__ void red_v4(float* p, float a, float b, float c, float d) {
    asm volatile("red.global.add.v4.f32 [%0], {%1,%2,%3,%4};"
                 :: "l"(p), "f"(a), "f"(b), "f"(c), "f"(d) : "memory");
}
__device__ __forceinline__ void cp16(uint32_t s, const void* g) {
    asm volatile("cp.async.cg.shared.global [%0], [%1], 16;" :: "r"(s), "l"(g));
}
__device__ __forceinline__ uint32_t pack_lo_bf16(float lox, float loy) {
    uint32_t r;
    asm("cvt.rn.bf16x2.f32 %0, %1, %2;" : "=r"(r) : "f"(loy), "f"(lox));
    return r;
}
// streaming load via cache-hint policy (evict_first) — legal on v4.f32
__device__ __forceinline__ float4 ldg_stream4(const float* p) {
    float4 v;
    uint64_t pol;
    asm("createpolicy.fractional.L2::evict_first.b64 %0, 1.0;" : "=l"(pol));
    asm("ld.global.nc.L2::cache_hint.v4.f32 {%0,%1,%2,%3}, [%4], %5;"
        : "=f"(v.x), "=f"(v.y), "=f"(v.z), "=f"(v.w) : "l"(p), "l"(pol));
    return v;
}
#define CP_COMMIT() asm volatile("cp.async.commit_group;" ::: "memory")
#define CP_WAIT0()  asm volatile("cp.async.wait_group 0;" ::: "memory")
#define CP_WAIT1()  asm volatile("cp.async.wait_group 1;" ::: "memory")

__device__ __forceinline__ void split4(float4 v, uint2& hp, uint2& lp) {
    uint32_t bx = __float_as_uint(v.x), by = __float_as_uint(v.y);
    uint32_t bz = __float_as_uint(v.z), bw = __float_as_uint(v.w);
    hp.x = __byte_perm(bx, by, 0x7632);
    hp.y = __byte_perm(bz, bw, 0x7632);
    lp.x = pack_lo_bf16(v.x - __uint_as_float(bx & 0xFFFF0000u),
                        v.y - __uint_as_float(by & 0xFFFF0000u));
    lp.y = pack_lo_bf16(v.z - __uint_as_float(bz & 0xFFFF0000u),
                        v.w - __uint_as_float(bw & 0xFFFF0000u));
}

// ---------------- mega scatter + wsplit (one launch) -------------------------------
__constant__ int c_ws_N[8]     = {256, 256, 256, 256, 256, 256, 128, 128};
__constant__ int c_ws_koff[8]  = {0, 0, 0, 128, 0, 128, 0, 0};
__constant__ int c_ws_kout[8]  = {128, 128, 256, 256, 256, 256, 256, 256};
__constant__ int c_ws_doff[8]  = {OFF_GA, OFF_GC, OFF_SA, OFF_SA, OFF_SC, OFF_SC, OFF_MA, OFF_MC};

struct MegaArgs {
    const float *x, *ea, *xcl, *cea;
    const int *ei_a, *ei_c, *ei_a2c, *ei_c2a;
    float *agg_atom, *agg_cl, *aggm_a2c, *cnt_a2c, *aggm_c2a, *cnt_c2a;
    const float* wsrc[8];
    __nv_bfloat16 *oh, *ol;
};

#define SCATTER_BLOCKS 100000
#define WSPLIT_BLOCKS  1024

__global__ void mega_scatter(MegaArgs A) {
    int b = blockIdx.x;
    if (b >= SCATTER_BLOCKS) {
        int i = (b - SCATTER_BLOCKS) * 256 + threadIdx.x;
        int seg = i >> 15;
        int w = i & 32767;
        int N = c_ws_N[seg];
        int k = w / N, n = w - k * N;
        float v = A.wsrc[seg][w];
        uint32_t bits = __float_as_uint(v);
        uint32_t hbits = bits & 0xFFFF0000u;
        float lo = v - __uint_as_float(hbits);
        size_t o = (size_t)n * c_ws_kout[seg] + c_ws_koff[seg] + k + c_ws_doff[seg];
        A.oh[o] = __ushort_as_bfloat16((unsigned short)(hbits >> 16));
        A.ol[o] = __float2bfloat16(lo);
        return;
    }
    int w = b * 8 + (threadIdx.x >> 5);
    int lane = threadIdx.x & 31;
    if (w < 600000) {
        int e = w;
        int src = A.ei_a[e];
        int dst = A.ei_a[EA + e];
        float4 xv = reinterpret_cast<const float4*>(A.x + (size_t)src * HD)[lane];
        float4 ev = ldg_stream4(A.ea + (size_t)e * HD + lane * 4);
        red_v4(A.agg_atom + (size_t)dst * HD + lane * 4,
               fmaxf(xv.x + ev.x, 0.0f), fmaxf(xv.y + ev.y, 0.0f),
               fmaxf(xv.z + ev.z, 0.0f), fmaxf(xv.w + ev.w, 0.0f));
    } else if (w < 700000) {
        int e = w - 600000;
        int src = A.ei_c[e];
        int dst = A.ei_c[EC + e];
        float4 xv = reinterpret_cast<const float4*>(A.xcl + (size_t)src * HD)[lane];
        float4 ev = ldg_stream4(A.cea + (size_t)e * HD + lane * 4);
        red_v4(A.agg_cl + (size_t)dst * HD + lane * 4,
               fmaxf(xv.x + ev.x, 0.0f), fmaxf(xv.y + ev.y, 0.0f),
               fmaxf(xv.z + ev.z, 0.0f), fmaxf(xv.w + ev.w, 0.0f));
    } else if (w < 750000) {
        int e0 = (w - 700000) * 2, e1 = e0 + 1;
        int s0 = A.ei_a2c[e0], s1 = A.ei_a2c[e1];
        int d0 = A.ei_a2c[EB + e0], d1 = A.ei_a2c[EB + e1];
        float4 v0 = reinterpret_cast<const float4*>(A.x + (size_t)s0 * HD)[lane];
        float4 v1 = reinterpret_cast<const float4*>(A.x + (size_t)s1 * HD)[lane];
        red_v4(A.aggm_a2c + (size_t)d0 * HD + lane * 4, v0.x, v0.y, v0.z, v0.w);
        red_v4(A.aggm_a2c + (size_t)d1 * HD + lane * 4, v1.x, v1.y, v1.z, v1.w);
        if (lane == 0) {
            atomicAdd(&A.cnt_a2c[d0], 1.0f);
            atomicAdd(&A.cnt_a2c[d1], 1.0f);
        }
    } else {
        int e0 = (w - 750000) * 2, e1 = e0 + 1;
        int s0 = A.ei_c2a[e0], s1 = A.ei_c2a[e1];
        int d0 = A.ei_c2a[EB + e0], d1 = A.ei_c2a[EB + e1];
        float4 v0 = reinterpret_cast<const float4*>(A.xcl + (size_t)s0 * HD)[lane];
        float4 v1 = reinterpret_cast<const float4*>(A.xcl + (size_t)s1 * HD)[lane];
        red_v4(A.aggm_c2a + (size_t)d0 * HD + lane * 4, v0.x, v0.y, v0.z, v0.w);
        red_v4(A.aggm_c2a + (size_t)d1 * HD + lane * 4, v1.x, v1.y, v1.z, v1.w);
        if (lane == 0) {
            atomicAdd(&A.cnt_c2a[d0], 1.0f);
            atomicAdd(&A.cnt_c2a[d1], 1.0f);
        }
    }
}

// ---------------- BN finalize (both sets, one launch) -----------------------------
__global__ void bn_finalize2(const float* __restrict__ sa, const float* __restrict__ sc,
                             const float* __restrict__ ga, const float* __restrict__ ba,
                             const float* __restrict__ gc, const float* __restrict__ bc,
                             float* __restrict__ scaleA, float* __restrict__ shiftA,
                             float* __restrict__ scaleC, float* __restrict__ shiftC) {
    int c = threadIdx.x & 255;
    if (threadIdx.x < 256) {
        float invM = 1.0f / NATOM;
        float mu = sa[c] * invM;
        float var = sa[PD + c] * invM - mu * mu;
        float s = ga[c] * rsqrtf(var + BN_EPS);
        scaleA[c] = s;
        shiftA[c] = ba[c] - mu * s;
    } else {
        float invM = 1.0f / NCL;
        float mu = sc[c] * invM;
        float var = sc[PD + c] * invM - mu * mu;
        float s = gc[c] * rsqrtf(var + BN_EPS);
        scaleC[c] = s;
        shiftC[c] = bc[c] - mu * s;
    }
}

// ---------------- GINE GEMM pair (round-10 structure) ------------------------------
#define SMO_AH   1024
#define SMO_AL   33792
#define SMO_BH   66560
#define SMEM_GINE (66560 + 256 * 256 * 2)

struct GineP {
    const float *A0, *A1;
    const __nv_bfloat16 *bh, *bl;
    const float *bias, *eps;
    float *stats, *C;
    int M;
};

__global__ __launch_bounds__(512)
void gine_gemm_pair(GineP Pa, GineP Pc) {
    constexpr int SMO_BL = SMO_BH + 256 * 256;
    const bool isA = blockIdx.x < GAC;
    const GineP P = isA ? Pa : Pc;
    const int m0 = (isA ? blockIdx.x : blockIdx.x - GAC) * 128;

    extern __shared__ char smem[];
    uint32_t sb = smem_u32(smem);
    const int tid = threadIdx.x;
    const int wid = tid >> 5;
    const int lid = tid & 31;
    const int wm = wid & 3;
    const int wn = wid >> 2;

    float* bias_s = reinterpret_cast<float*>(smem);
    if (tid < 256) bias_s[tid] = P.bias[tid];

    const float ef = 1.0f + *P.eps;

    float acc[2][8][4];
#pragma unroll
    for (int mt = 0; mt < 2; mt++)
#pragma unroll
        for (int nt = 0; nt < 8; nt++)
#pragma unroll
            for (int j = 0; j < 4; j++) acc[mt][nt][j] = 0.0f;

#pragma unroll
    for (int it = 0; it < 8; it++) {
        int idx = tid + it * 512;
        int n = idx >> 4;
        int ch = idx & 15;
        uint32_t off = n * 256 + ((ch ^ (n & 7)) << 4);
        cp16(sb + SMO_BH + off, P.bh + (size_t)n * 128 + ch * 8);
        cp16(sb + SMO_BL + off, P.bl + (size_t)n * 128 + ch * 8);
    }
    CP_COMMIT();

#pragma unroll
    for (int it = 0; it < 8; it++) {
        int idx = tid + it * 512;
        int r = idx >> 5;
        int c4 = (idx & 31) * 4;
        int gr = m0 + r;
        float4 v = make_float4(0.f, 0.f, 0.f, 0.f);
        if (gr < P.M) {
            float4 a = *reinterpret_cast<const float4*>(P.A0 + (size_t)gr * 128 + c4);
            float4 g = *reinterpret_cast<const float4*>(P.A1 + (size_t)gr * 128 + c4);
            v.x = fmaf(ef, a.x, g.x); v.y = fmaf(ef, a.y, g.y);
            v.z = fmaf(ef, a.z, g.z); v.w = fmaf(ef, a.w, g.w);
        }
        uint2 hp, lp;
        split4(v, hp, lp);
        uint32_t off = r * 256 + (((c4 >> 3) ^ (r & 7)) << 4) + ((c4 & 4) << 1);
        *reinterpret_cast<uint2*>(smem + SMO_AH + off) = hp;
        *reinterpret_cast<uint2*>(smem + SMO_AL + off) = lp;
    }
    CP_WAIT0();
    __syncthreads();

    const int arow = wm * 32 + (lid & 15);
    const int akp = lid >> 4;
    const int bn = wn * 64 + (lid & 7) + ((lid >> 4) << 3);
    const int bkp = (lid >> 3) & 1;
#pragma unroll
    for (int ks = 0; ks < 8; ks++) {
        uint32_t ah[2][4], al[2][4];
#pragma unroll
        for (int mt = 0; mt < 2; mt++) {
            int r = arow + mt * 16;
            uint32_t ch = (uint32_t)((ks * 2 + akp) ^ (r & 7));
            uint32_t off = r * 256 + (ch << 4);
            ldm_x4(ah[mt], sb + SMO_AH + off);
            ldm_x4(al[mt], sb + SMO_AL + off);
        }
#pragma unroll
        for (int np = 0; np < 4; np++) {
            int n = bn + np * 16;
            uint32_t ch = (uint32_t)((ks * 2 + bkp) ^ (n & 7));
            uint32_t off = n * 256 + (ch << 4);
            uint32_t bh[4], bl[4];
            ldm_x4(bh, sb + SMO_BH + off);
            ldm_x4(bl, sb + SMO_BL + off);
#pragma unroll
            for (int mt = 0; mt < 2; mt++) {
#pragma unroll
                for (int sn = 0; sn < 2; sn++) {
                    float* c = acc[mt][np * 2 + sn];
                    mma16816(c, ah[mt], bh + sn * 2);
                    mma16816(c, ah[mt], bl + sn * 2);
                    mma16816(c, al[mt], bh + sn * 2);
                }
            }
        }
    }

    const int g = lid >> 2;
    const int tig = lid & 3;
#pragma unroll
    for (int nt = 0; nt < 8; nt++) {
        int nl = wn * 64 + nt * 8 + 2 * tig;
        float b0 = bias_s[nl], b1 = bias_s[nl + 1];
        float s0 = 0.f, s1 = 0.f, q0 = 0.f, q1 = 0.f;
#pragma unroll
        for (int mt = 0; mt < 2; mt++) {
            int m = m0 + wm * 32 + mt * 16 + g;
            if (m < P.M) {
                float ox = acc[mt][nt][0] + b0, oy = acc[mt][nt][1] + b1;
                *reinterpret_cast<float2*>(P.C + (size_t)m * PD + nl) = make_float2(ox, oy);
                s0 += ox; s1 += oy; q0 += ox * ox; q1 += oy * oy;
            }
            if (m + 8 < P.M) {
                float ox = acc[mt][nt][2] + b0, oy = acc[mt][nt][3] + b1;
                *reinterpret_cast<float2*>(P.C + (size_t)(m + 8) * PD + nl) = make_float2(ox, oy);
                s0 += ox; s1 += oy; q0 += ox * ox; q1 += oy * oy;
            }
        }
#pragma unroll
        for (int d = 4; d < 32; d <<= 1) {
            s0 += __shfl_xor_sync(0xFFFFFFFFu, s0, d);
            s1 += __shfl_xor_sync(0xFFFFFFFFu, s1, d);
            q0 += __shfl_xor_sync(0xFFFFFFFFu, q0, d);
            q1 += __shfl_xor_sync(0xFFFFFFFFu, q1, d);
        }
        if (g == 0) {
            atomicAdd(P.stats + nl, s0);
            atomicAdd(P.stats + nl + 1, s1);
            atomicAdd(P.stats + PD + nl, q0);
            atomicAdd(P.stats + PD + nl + 1, q1);
        }
    }
}

// ---------------- fused SAGE + MERGE pair (round-10 + phase-3 prefetch) -------------
#define F_BIAS1 0
#define F_BIAS2 1024
#define F_SCALE 1536
#define F_SHIFT 2560
#define F_A1H   4096
#define F_A1L   36864
#define F_B1H   69632
#define F_B1L   135168
#define F_A2H   F_B1H
#define F_A2L   F_B1L
#define F_B2    F_A1H
#define SMEM_FUSED 200704

struct FusedP {
    const float *aggm, *xdst, *cnt;
    const __nv_bfloat16 *b1h, *b1l;
    const float *sbl, *sbr, *pre, *scale, *shift;
    const __nv_bfloat16 *b2h, *b2l;
    const float *mbias;
    float *C;
    int M;
};

__global__ __launch_bounds__(512)
void sage_merge_pair(FusedP Pa, FusedP Pc) {
    const bool isA = blockIdx.x < GAC;
    const FusedP P = isA ? Pa : Pc;
    const int m0 = (isA ? blockIdx.x : blockIdx.x - GAC) * 128;

    extern __shared__ char smem[];
    uint32_t sb = smem_u32(smem);
    const int tid = threadIdx.x;
    const int wid = tid >> 5;
    const int lid = tid & 31;

    float* bias1_s = reinterpret_cast<float*>(smem + F_BIAS1);
    float* bias2_s = reinterpret_cast<float*>(smem + F_BIAS2);
    float* scale_s = reinterpret_cast<float*>(smem + F_SCALE);
    float* shift_s = reinterpret_cast<float*>(smem + F_SHIFT);
    if (tid < 256) {
        bias1_s[tid] = P.sbl[tid] + P.sbr[tid];
        scale_s[tid] = P.scale[tid];
        shift_s[tid] = P.shift[tid];
    } else if (tid < 384) {
        bias2_s[tid - 256] = P.mbias[tid - 256];
    }

    // ===== Phase 1: SAGE GEMM (K=256), 2 chunks of k=128 =====
    const int wm = wid & 3;
    const int wn = wid >> 2;
    float acc[2][8][4];
#pragma unroll
    for (int mt = 0; mt < 2; mt++)
#pragma unroll
        for (int nt = 0; nt < 8; nt++)
#pragma unroll
            for (int j = 0; j < 4; j++) acc[mt][nt][j] = 0.0f;

    for (int kk = 0; kk < 256; kk += 128) {
#pragma unroll
        for (int it = 0; it < 8; it++) {
            int idx = tid + it * 512;
            int n = idx >> 4;
            int ch = idx & 15;
            uint32_t off = n * 256 + ((ch ^ (n & 7)) << 4);
            cp16(sb + F_B1H + off, P.b1h + (size_t)n * 256 + kk + ch * 8);
            cp16(sb + F_B1L + off, P.b1l + (size_t)n * 256 + kk + ch * 8);
        }
        CP_COMMIT();

#pragma unroll
        for (int it = 0; it < 8; it++) {
            int idx = tid + it * 512;
            int r = idx >> 5;
            int c4 = (idx & 31) * 4;
            int gr = m0 + r;
            int gk = kk + c4;
            float4 v = make_float4(0.f, 0.f, 0.f, 0.f);
            if (gr < P.M) {
                if (gk < 128) {
                    float4 a = *reinterpret_cast<const float4*>(P.aggm + (size_t)gr * 128 + gk);
                    float inv = __frcp_rn(fmaxf(P.cnt[gr], 1.0f));
                    v.x = a.x * inv; v.y = a.y * inv; v.z = a.z * inv; v.w = a.w * inv;
                } else {
                    v = *reinterpret_cast<const float4*>(P.xdst + (size_t)gr * 128 + (gk - 128));
                }
            }
            uint2 hp, lp;
            split4(v, hp, lp);
            uint32_t off = r * 256 + (((c4 >> 3) ^ (r & 7)) << 4) + ((c4 & 4) << 1);
            *reinterpret_cast<uint2*>(smem + F_A1H + off) = hp;
            *reinterpret_cast<uint2*>(smem + F_A1L + off) = lp;
        }
        CP_WAIT0();
        __syncthreads();

        const int arow = wm * 32 + (lid & 15);
        const int akp = lid >> 4;
        const int bn = wn * 64 + (lid & 7) + ((lid >> 4) << 3);
        const int bkp = (lid >> 3) & 1;
#pragma unroll
        for (int ks = 0; ks < 8; ks++) {
            uint32_t ah[2][4], al[2][4];
#pragma unroll
            for (int mt = 0; mt < 2; mt++) {
                int r = arow + mt * 16;
                uint32_t ch = (uint32_t)((ks * 2 + akp) ^ (r & 7));
                uint32_t off = r * 256 + (ch << 4);
                ldm_x4(ah[mt], sb + F_A1H + off);
                ldm_x4(al[mt], sb + F_A1L + off);
            }
#pragma unroll
            for (int np = 0; np < 4; np++) {
                int n = bn + np * 16;
                uint32_t ch = (uint32_t)((ks * 2 + bkp) ^ (n & 7));
                uint32_t off = n * 256 + (ch << 4);
                uint32_t bh[4], blx[4];
                ldm_x4(bh, sb + F_B1H + off);
                ldm_x4(blx, sb + F_B1L + off);
#pragma unroll
                for (int mt = 0; mt < 2; mt++) {
#pragma unroll
                    for (int sn = 0; sn < 2; sn++) {
                        float* c = acc[mt][np * 2 + sn];
                        mma16816(c, ah[mt], bh + sn * 2);
                        mma16816(c, ah[mt], blx + sn * 2);
                        mma16816(c, al[mt], bh + sn * 2);
                    }
                }
            }
        }
        __syncthreads();
    }

    // ===== B2 prefetch: chunks 0,1 of 4 (k=64) into freed A1 region =====
    auto loadB2 = [&](int c, int b) {
#pragma unroll
        for (int it = 0; it < 2; it++) {
            int idx = tid + it * 512;          // 0..1023
            int n = idx >> 3;
            int ch = idx & 7;
            uint32_t off = n * 128 + ((ch ^ (n & 7)) << 4);
            cp16(sb + F_B2 + b * 32768 + off, P.b2h + (size_t)n * 256 + c * 64 + ch * 8);
            cp16(sb + F_B2 + b * 32768 + 16384 + off, P.b2l + (size_t)n * 256 + c * 64 + ch * 8);
        }
        CP_COMMIT();
    };
    loadB2(0, 0);
    loadB2(1, 1);

    // ===== Phase 2: A2 = relu(pre*scale+shift) + S + bias -> smem split bf16 =====
    {
        const int g = lid >> 2;
        const int tig = lid & 3;
#pragma unroll
        for (int nt = 0; nt < 8; nt++) {
            int nl = wn * 64 + nt * 8 + 2 * tig;
            float b0 = bias1_s[nl], b1 = bias1_s[nl + 1];
            float sc0 = scale_s[nl], sc1 = scale_s[nl + 1];
            float sh0 = shift_s[nl], sh1 = shift_s[nl + 1];
#pragma unroll
            for (int mt = 0; mt < 2; mt++) {
#pragma unroll
                for (int half = 0; half < 2; half++) {
                    int r = wm * 32 + mt * 16 + g + half * 8;
                    int m = m0 + r;
                    float ax = 0.f, ay = 0.f;
                    if (m < P.M) {
                        float2 p = *reinterpret_cast<const float2*>(P.pre + (size_t)m * PD + nl);
                        ax = fmaxf(fmaf(p.x, sc0, sh0), 0.f) + acc[mt][nt][half * 2 + 0] + b0;
                        ay = fmaxf(fmaf(p.y, sc1, sh1), 0.f) + acc[mt][nt][half * 2 + 1] + b1;
                    }
                    uint32_t bx = __float_as_uint(ax), by = __float_as_uint(ay);
                    uint32_t hp = __byte_perm(bx, by, 0x7632);
                    uint32_t lp = pack_lo_bf16(ax - __uint_as_float(bx & 0xFFFF0000u),
                                               ay - __uint_as_float(by & 0xFFFF0000u));
                    uint32_t off = r * 512 + (((nl >> 3) ^ (r & 7)) << 4) + (nl & 7) * 2;
                    *reinterpret_cast<uint32_t*>(smem + F_A2H + off) = hp;
                    *reinterpret_cast<uint32_t*>(smem + F_A2L + off) = lp;
                }
            }
        }
    }
    __syncthreads();

    // ===== Phase 3: merge GEMM from smem A2, 4 chunks k=64, double-buffered B2 =====
    const int wm2 = wid & 7;
    const int wn2 = wid >> 3;
    float acc2[8][4];
#pragma unroll
    for (int nt = 0; nt < 8; nt++)
#pragma unroll
        for (int j = 0; j < 4; j++) acc2[nt][j] = 0.0f;

    const int arow2 = wm2 * 16 + (lid & 15);
    const int akp2 = lid >> 4;
    const int bn2 = wn2 * 64 + (lid & 7) + ((lid >> 4) << 3);
    const int bkp2 = (lid >> 3) & 1;

    auto mma2 = [&](int c, int b) {
        uint32_t bbase = sb + F_B2 + b * 32768;
#pragma unroll
        for (int ks = 0; ks < 4; ks++) {
            uint32_t ah[4], al[4];
            {
                int r = arow2;
                uint32_t ch = (uint32_t)((c * 8 + ks * 2 + akp2) ^ (r & 7));
                uint32_t off = r * 512 + (ch << 4);
                ldm_x4(ah, sb + F_A2H + off);
                ldm_x4(al, sb + F_A2L + off);
            }
#pragma unroll
            for (int np = 0; np < 4; np++) {
                int n = bn2 + np * 16;
                uint32_t ch = (uint32_t)((ks * 2 + bkp2) ^ (n & 7));
                uint32_t off = n * 128 + (ch << 4);
                uint32_t bh[4], blx[4];
                ldm_x4(bh, bbase + off);
                ldm_x4(blx, bbase + 16384 + off);
#pragma unroll
                for (int sn = 0; sn < 2; sn++) {
                    float* cc = acc2[np * 2 + sn];
                    mma16816(cc, ah, bh + sn * 2);
                    mma16816(cc, ah, blx + sn * 2);
                    mma16816(cc, al, bh + sn * 2);
                }
            }
        }
    };

#pragma unroll
    for (int c = 0; c < 4; c++) {
        if (c == 3) CP_WAIT0(); else CP_WAIT1();
        __syncthreads();
        mma2(c, c & 1);
        __syncthreads();
        if (c < 2) loadB2(c + 2, c & 1);
    }

    // ===== epilogue =====
    {
        const int g = lid >> 2;
        const int tig = lid & 3;
#pragma unroll
        for (int nt = 0; nt < 8; nt++) {
            int nl = wn2 * 64 + nt * 8 + 2 * tig;
            float b0 = bias2_s[nl], b1 = bias2_s[nl + 1];
            int m = m0 + wm2 * 16 + g;
            if (m < P.M) {
                *reinterpret_cast<float2*>(P.C + (size_t)m * HD + nl) =
                    make_float2(acc2[nt][0] + b0, acc2[nt][1] + b1);
            }
            if (m + 8 < P.M) {
                *reinterpret_cast<float2*>(P.C + (size_t)(m + 8) * HD + nl) =
                    make_float2(acc2[nt][2] + b0, acc2[nt][3] + b1);
            }
        }
    }
}

// -----------------------------------------------------------------------------------
extern "C" void kernel_launch(void* const* d_in, const int* in_sizes, int n_in,
                              void* d_out, int out_size) {
    const float* x         = (const float*)d_in[0];
    const float* edge_attr = (const float*)d_in[1];
    const float* x_cl      = (const float*)d_in[2];
    const float* c2c_ea    = (const float*)d_in[3];

    int pbase, ebase;
    if (in_sizes[4] == 2 * EA) { ebase = 4; pbase = 8; }
    else                       { pbase = 4; ebase = 26; }

    const int* ei_a   = (const int*)d_in[ebase + 0];
    const int* ei_c2c = (const int*)d_in[ebase + 1];
    const int* ei_a2c = (const int*)d_in[ebase + 2];
    const int* ei_c2a = (const int*)d_in[ebase + 3];

    const float* atom_eps   = (const float*)d_in[pbase + 0];
    const float* atom_W     = (const float*)d_in[pbase + 1];
    const float* atom_b     = (const float*)d_in[pbase + 2];
    const float* atom_gamma = (const float*)d_in[pbase + 3];
    const float* atom_beta  = (const float*)d_in[pbase + 4];
    const float* cl_eps     = (const float*)d_in[pbase + 5];
    const float* cl_W       = (const float*)d_in[pbase + 6];
    const float* cl_b       = (const float*)d_in[pbase + 7];
    const float* cl_gamma   = (const float*)d_in[pbase + 8];
    const float* cl_beta    = (const float*)d_in[pbase + 9];
    const float* a2c_Wl     = (const float*)d_in[pbase + 10];
    const float* a2c_bl     = (const float*)d_in[pbase + 11];
    const float* a2c_Wr     = (const float*)d_in[pbase + 12];
    const float* a2c_br     = (const float*)d_in[pbase + 13];
    const float* c2a_Wl     = (const float*)d_in[pbase + 14];
    const float* c2a_bl     = (const float*)d_in[pbase + 15];
    const float* c2a_Wr     = (const float*)d_in[pbase + 16];
    const float* c2a_br     = (const float*)d_in[pbase + 17];
    const float* merge_atom_W = (const float*)d_in[pbase + 18];
    const float* merge_atom_b = (const float*)d_in[pbase + 19];
    const float* merge_cl_W   = (const float*)d_in[pbase + 20];
    const float* merge_cl_b   = (const float*)d_in[pbase + 21];

    float* out = (float*)d_out;

    float *p_zero, *p_pre_atom, *p_pre_cl;
    float *p_scale_atom, *p_shift_atom, *p_scale_cl, *p_shift_cl;
    __nv_bfloat16 *p_Bt_hi, *p_Bt_lo;
    cudaGetSymbolAddress((void**)&p_zero, g_zero);
    cudaGetSymbolAddress((void**)&p_pre_atom, g_pre_atom);
    cudaGetSymbolAddress((void**)&p_pre_cl, g_pre_cl);
    cudaGetSymbolAddress((void**)&p_scale_atom, g_scale_atom);
    cudaGetSymbolAddress((void**)&p_shift_atom, g_shift_atom);
    cudaGetSymbolAddress((void**)&p_scale_cl, g_scale_cl);
    cudaGetSymbolAddress((void**)&p_shift_cl, g_shift_cl);
    cudaGetSymbolAddress((void**)&p_Bt_hi, g_Bt_hi);
    cudaGetSymbolAddress((void**)&p_Bt_lo, g_Bt_lo);

    float* p_agg_atom   = p_zero + Z_AGG_ATOM;
    float* p_agg_cl     = p_zero + Z_AGG_CL;
    float* p_aggm_c2a   = p_zero + Z_AGGM_C2A;
    float* p_aggm_a2c   = p_zero + Z_AGGM_A2C;
    float* p_cnt_c2a    = p_zero + Z_CNT_C2A;
    float* p_cnt_a2c    = p_zero + Z_CNT_A2C;
    float* p_stats_atom = p_zero + Z_STATS_A;
    float* p_stats_cl   = p_zero + Z_STATS_C;

    cudaMemsetAsync(p_zero, 0, (size_t)Z_TOTAL * 4, 0);

    cudaFuncSetAttribute((const void*)gine_gemm_pair,
                         cudaFuncAttributeMaxDynamicSharedMemorySize, SMEM_GINE);
    cudaFuncSetAttribute((const void*)sage_merge_pair,
                         cudaFuncAttributeMaxDynamicSharedMemorySize, SMEM_FUSED);

    // ---- mega scatter + wsplit ----
    {
        MegaArgs A;
        A.x = x; A.ea = edge_attr; A.xcl = x_cl; A.cea = c2c_ea;
        A.ei_a = ei_a; A.ei_c = ei_c2c; A.ei_a2c = ei_a2c; A.ei_c2a = ei_c2a;
        A.agg_atom = p_agg_atom; A.agg_cl = p_agg_cl;
        A.aggm_a2c = p_aggm_a2c; A.cnt_a2c = p_cnt_a2c;
        A.aggm_c2a = p_aggm_c2a; A.cnt_c2a = p_cnt_c2a;
        A.wsrc[0] = atom_W;  A.wsrc[1] = cl_W;
        A.wsrc[2] = c2a_Wl;  A.wsrc[3] = c2a_Wr;
        A.wsrc[4] = a2c_Wl;  A.wsrc[5] = a2c_Wr;
        A.wsrc[6] = merge_atom_W; A.wsrc[7] = merge_cl_W;
        A.oh = p_Bt_hi; A.ol = p_Bt_lo;
        mega_scatter<<<SCATTER_BLOCKS + WSPLIT_BLOCKS, 256>>>(A);
    }

    // ---- GINE GEMM pair ----
    {
        GineP Pa{x, p_agg_atom, p_Bt_hi + OFF_GA, p_Bt_lo + OFF_GA,
                 atom_b, atom_eps, p_stats_atom, p_pre_atom, NATOM};
        GineP Pc{x_cl, p_agg_cl, p_Bt_hi + OFF_GC, p_Bt_lo + OFF_GC,
                 cl_b, cl_eps, p_stats_cl, p_pre_cl, NCL};
        gine_gemm_pair<<<GAC + GCC, 512, SMEM_GINE>>>(Pa, Pc);
    }

    bn_finalize2<<<1, 512>>>(p_stats_atom, p_stats_cl, atom_gamma, atom_beta,
                             cl_gamma, cl_beta, p_scale_atom, p_shift_atom,
                             p_scale_cl, p_shift_cl);

    // ---- fused SAGE + MERGE pair ----
    {
        FusedP Pa{p_aggm_c2a, x, p_cnt_c2a,
                  p_Bt_hi + OFF_SA, p_Bt_lo + OFF_SA, c2a_bl, c2a_br,
                  p_pre_atom, p_scale_atom, p_shift_atom,
                  p_Bt_hi + OFF_MA, p_Bt_lo + OFF_MA, merge_atom_b, out, NATOM};
        FusedP Pc{p_aggm_a2c, x_cl, p_cnt_a2c,
                  p_Bt_hi + OFF_SC, p_Bt_lo + OFF_SC, a2c_bl, a2c_br,
                  p_pre_cl, p_scale_cl, p_shift_cl,
                  p_Bt_hi + OFF_MC, p_Bt_lo + OFF_MC, merge_cl_b,
                  out + (size_t)NATOM * HD, NCL};
        sage_merge_pair<<<GAC + GCC, 512, SMEM_FUSED>>>(Pa, Pc);
    }
}

// round 14
// speedup vs baseline: 1.1003x; 1.0318x over previous
#include <cuda_runtime.h>
#include <cuda_bf16.h>
#include <cstdint>
#include <cstddef>

#define NATOM 100000
#define NCL   25000
#define EA    600000
#define EC    100000
#define EB    100000
#define HD    128
#define PD    256
#define BN_EPS 1e-5f
#define GAC   782
#define GCC   196

// ---------------- zeroed scratch arena (single memset) -----------------------------
#define Z_AGG_ATOM  0
#define Z_AGG_CL    12800000
#define Z_AGGM_C2A  16000000
#define Z_AGGM_A2C  28800000
#define Z_CNT_C2A   32000000
#define Z_CNT_A2C   32100000
#define Z_STATS_A   32125000
#define Z_STATS_C   32125512
#define Z_TOTAL     32126024
__device__ float g_zero[Z_TOTAL];

__device__ float g_pre_atom[(size_t)NATOM * PD];
__device__ float g_pre_cl[(size_t)NCL * PD];

#define OFF_GA 0
#define OFF_GC 32768
#define OFF_SA 65536
#define OFF_SC 131072
#define OFF_MA 196608
#define OFF_MC 229376
__device__ __nv_bfloat16 g_Bt_hi[262144];
__device__ __nv_bfloat16 g_Bt_lo[262144];

// ---------------- helpers ---------------------------------------------------------
__device__ __forceinline__ uint32_t smem_u32(const void* p) {
    uint32_t a;
    asm("{ .reg .u64 t; cvta.to.shared.u64 t, %1; cvt.u32.u64 %0, t; }" : "=r"(a) : "l"(p));
    return a;
}
__device__ __forceinline__ void ldm_x4(uint32_t* r, uint32_t addr) {
    asm volatile("ldmatrix.sync.aligned.m8n8.x4.shared.b16 {%0,%1,%2,%3}, [%4];"
                 : "=r"(r[0]), "=r"(r[1]), "=r"(r[2]), "=r"(r[3]) : "r"(addr));
}
__device__ __forceinline__ void mma16816(float* c, const uint32_t* a, const uint32_t* b) {
    asm volatile("mma.sync.aligned.m16n8k16.row.col.f32.bf16.bf16.f32 "
                 "{%0,%1,%2,%3}, {%4,%5,%6,%7}, {%8,%9}, {%0,%1,%2,%3};"
                 : "+f"(c[0]), "+f"(c[1]), "+f"(c[2]), "+f"(c[3])
                 : "r"(a[0]), "r"(a[1]), "r"(a[2]), "r"(a[3]), "r"(b[0]), "r"(b[1]));
}
__device__ __forceinline__ void red_v4(float* p, float a, float b, float c, float d) {
    asm volatile("red.global.add.v4.f32 [%0], {%1,%2,%3,%4};"
                 :: "l"(p), "f"(a), "f"(b), "f"(c), "f"(d) : "memory");
}
__device__ __forceinline__ void cp16(uint32_t s, const void* g) {
    asm volatile("cp.async.cg.shared.global [%0], [%1], 16;" :: "r"(s), "l"(g));
}
__device__ __forceinline__ uint32_t pack_lo_bf16(float lox, float loy) {
    uint32_t r;
    asm("cvt.rn.bf16x2.f32 %0, %1, %2;" : "=r"(r) : "f"(loy), "f"(lox));
    return r;
}
__device__ __forceinline__ float4 ldg_stream4(const float* p) {
    float4 v;
    uint64_t pol;
    asm("createpolicy.fractional.L2::evict_first.b64 %0, 1.0;" : "=l"(pol));
    asm("ld.global.nc.L2::cache_hint.v4.f32 {%0,%1,%2,%3}, [%4], %5;"
        : "=f"(v.x), "=f"(v.y), "=f"(v.z), "=f"(v.w) : "l"(p), "l"(pol));
    return v;
}
#define CP_COMMIT() asm volatile("cp.async.commit_group;" ::: "memory")
#define CP_WAIT0()  asm volatile("cp.async.wait_group 0;" ::: "memory")
#define CP_WAIT1()  asm volatile("cp.async.wait_group 1;" ::: "memory")

__device__ __forceinline__ void split4(float4 v, uint2& hp, uint2& lp) {
    uint32_t bx = __float_as_uint(v.x), by = __float_as_uint(v.y);
    uint32_t bz = __float_as_uint(v.z), bw = __float_as_uint(v.w);
    hp.x = __byte_perm(bx, by, 0x7632);
    hp.y = __byte_perm(bz, bw, 0x7632);
    lp.x = pack_lo_bf16(v.x - __uint_as_float(bx & 0xFFFF0000u),
                        v.y - __uint_as_float(by & 0xFFFF0000u));
    lp.y = pack_lo_bf16(v.z - __uint_as_float(bz & 0xFFFF0000u),
                        v.w - __uint_as_float(bw & 0xFFFF0000u));
}

// ---------------- mega scatter + wsplit (one launch, unchanged) --------------------
__constant__ int c_ws_N[8]     = {256, 256, 256, 256, 256, 256, 128, 128};
__constant__ int c_ws_koff[8]  = {0, 0, 0, 128, 0, 128, 0, 0};
__constant__ int c_ws_kout[8]  = {128, 128, 256, 256, 256, 256, 256, 256};
__constant__ int c_ws_doff[8]  = {OFF_GA, OFF_GC, OFF_SA, OFF_SA, OFF_SC, OFF_SC, OFF_MA, OFF_MC};

struct MegaArgs {
    const float *x, *ea, *xcl, *cea;
    const int *ei_a, *ei_c, *ei_a2c, *ei_c2a;
    float *agg_atom, *agg_cl, *aggm_a2c, *cnt_a2c, *aggm_c2a, *cnt_c2a;
    const float* wsrc[8];
    __nv_bfloat16 *oh, *ol;
};

#define SCATTER_BLOCKS 100000
#define WSPLIT_BLOCKS  1024

__global__ void mega_scatter(MegaArgs A) {
    int b = blockIdx.x;
    if (b >= SCATTER_BLOCKS) {
        int i = (b - SCATTER_BLOCKS) * 256 + threadIdx.x;
        int seg = i >> 15;
        int w = i & 32767;
        int N = c_ws_N[seg];
        int k = w / N, n = w - k * N;
        float v = A.wsrc[seg][w];
        uint32_t bits = __float_as_uint(v);
        uint32_t hbits = bits & 0xFFFF0000u;
        float lo = v - __uint_as_float(hbits);
        size_t o = (size_t)n * c_ws_kout[seg] + c_ws_koff[seg] + k + c_ws_doff[seg];
        A.oh[o] = __ushort_as_bfloat16((unsigned short)(hbits >> 16));
        A.ol[o] = __float2bfloat16(lo);
        return;
    }
    int w = b * 8 + (threadIdx.x >> 5);
    int lane = threadIdx.x & 31;
    if (w < 600000) {
        int e = w;
        int src = A.ei_a[e];
        int dst = A.ei_a[EA + e];
        float4 xv = reinterpret_cast<const float4*>(A.x + (size_t)src * HD)[lane];
        float4 ev = ldg_stream4(A.ea + (size_t)e * HD + lane * 4);
        red_v4(A.agg_atom + (size_t)dst * HD + lane * 4,
               fmaxf(xv.x + ev.x, 0.0f), fmaxf(xv.y + ev.y, 0.0f),
               fmaxf(xv.z + ev.z, 0.0f), fmaxf(xv.w + ev.w, 0.0f));
    } else if (w < 700000) {
        int e = w - 600000;
        int src = A.ei_c[e];
        int dst = A.ei_c[EC + e];
        float4 xv = reinterpret_cast<const float4*>(A.xcl + (size_t)src * HD)[lane];
        float4 ev = ldg_stream4(A.cea + (size_t)e * HD + lane * 4);
        red_v4(A.agg_cl + (size_t)dst * HD + lane * 4,
               fmaxf(xv.x + ev.x, 0.0f), fmaxf(xv.y + ev.y, 0.0f),
               fmaxf(xv.z + ev.z, 0.0f), fmaxf(xv.w + ev.w, 0.0f));
    } else if (w < 750000) {
        int e0 = (w - 700000) * 2, e1 = e0 + 1;
        int s0 = A.ei_a2c[e0], s1 = A.ei_a2c[e1];
        int d0 = A.ei_a2c[EB + e0], d1 = A.ei_a2c[EB + e1];
        float4 v0 = reinterpret_cast<const float4*>(A.x + (size_t)s0 * HD)[lane];
        float4 v1 = reinterpret_cast<const float4*>(A.x + (size_t)s1 * HD)[lane];
        red_v4(A.aggm_a2c + (size_t)d0 * HD + lane * 4, v0.x, v0.y, v0.z, v0.w);
        red_v4(A.aggm_a2c + (size_t)d1 * HD + lane * 4, v1.x, v1.y, v1.z, v1.w);
        if (lane == 0) {
            atomicAdd(&A.cnt_a2c[d0], 1.0f);
            atomicAdd(&A.cnt_a2c[d1], 1.0f);
        }
    } else {
        int e0 = (w - 750000) * 2, e1 = e0 + 1;
        int s0 = A.ei_c2a[e0], s1 = A.ei_c2a[e1];
        int d0 = A.ei_c2a[EB + e0], d1 = A.ei_c2a[EB + e1];
        float4 v0 = reinterpret_cast<const float4*>(A.xcl + (size_t)s0 * HD)[lane];
        float4 v1 = reinterpret_cast<const float4*>(A.xcl + (size_t)s1 * HD)[lane];
        red_v4(A.aggm_c2a + (size_t)d0 * HD + lane * 4, v0.x, v0.y, v0.z, v0.w);
        red_v4(A.aggm_c2a + (size_t)d1 * HD + lane * 4, v1.x, v1.y, v1.z, v1.w);
        if (lane == 0) {
            atomicAdd(&A.cnt_c2a[d0], 1.0f);
            atomicAdd(&A.cnt_c2a[d1], 1.0f);
        }
    }
}

// ---------------- GINE GEMM pair (round-13 structure, unchanged) -------------------
#define SMO_AH   1024
#define SMO_AL   33792
#define SMO_BH   66560
#define SMEM_GINE (66560 + 256 * 256 * 2)

struct GineP {
    const float *A0, *A1;
    const __nv_bfloat16 *bh, *bl;
    const float *bias, *eps;
    float *stats, *C;
    int M;
};

__global__ __launch_bounds__(512)
void gine_gemm_pair(GineP Pa, GineP Pc) {
    constexpr int SMO_BL = SMO_BH + 256 * 256;
    const bool isA = blockIdx.x < GAC;
    const GineP P = isA ? Pa : Pc;
    const int m0 = (isA ? blockIdx.x : blockIdx.x - GAC) * 128;

    extern __shared__ char smem[];
    uint32_t sb = smem_u32(smem);
    const int tid = threadIdx.x;
    const int wid = tid >> 5;
    const int lid = tid & 31;
    const int wm = wid & 3;
    const int wn = wid >> 2;

    float* bias_s = reinterpret_cast<float*>(smem);
    if (tid < 256) bias_s[tid] = P.bias[tid];

    const float ef = 1.0f + *P.eps;

    float acc[2][8][4];
#pragma unroll
    for (int mt = 0; mt < 2; mt++)
#pragma unroll
        for (int nt = 0; nt < 8; nt++)
#pragma unroll
            for (int j = 0; j < 4; j++) acc[mt][nt][j] = 0.0f;

#pragma unroll
    for (int it = 0; it < 8; it++) {
        int idx = tid + it * 512;
        int n = idx >> 4;
        int ch = idx & 15;
        uint32_t off = n * 256 + ((ch ^ (n & 7)) << 4);
        cp16(sb + SMO_BH + off, P.bh + (size_t)n * 128 + ch * 8);
        cp16(sb + SMO_BL + off, P.bl + (size_t)n * 128 + ch * 8);
    }
    CP_COMMIT();

#pragma unroll
    for (int it = 0; it < 8; it++) {
        int idx = tid + it * 512;
        int r = idx >> 5;
        int c4 = (idx & 31) * 4;
        int gr = m0 + r;
        float4 v = make_float4(0.f, 0.f, 0.f, 0.f);
        if (gr < P.M) {
            float4 a = *reinterpret_cast<const float4*>(P.A0 + (size_t)gr * 128 + c4);
            float4 g = *reinterpret_cast<const float4*>(P.A1 + (size_t)gr * 128 + c4);
            v.x = fmaf(ef, a.x, g.x); v.y = fmaf(ef, a.y, g.y);
            v.z = fmaf(ef, a.z, g.z); v.w = fmaf(ef, a.w, g.w);
        }
        uint2 hp, lp;
        split4(v, hp, lp);
        uint32_t off = r * 256 + (((c4 >> 3) ^ (r & 7)) << 4) + ((c4 & 4) << 1);
        *reinterpret_cast<uint2*>(smem + SMO_AH + off) = hp;
        *reinterpret_cast<uint2*>(smem + SMO_AL + off) = lp;
    }
    CP_WAIT0();
    __syncthreads();

    const int arow = wm * 32 + (lid & 15);
    const int akp = lid >> 4;
    const int bn = wn * 64 + (lid & 7) + ((lid >> 4) << 3);
    const int bkp = (lid >> 3) & 1;
#pragma unroll
    for (int ks = 0; ks < 8; ks++) {
        uint32_t ah[2][4], al[2][4];
#pragma unroll
        for (int mt = 0; mt < 2; mt++) {
            int r = arow + mt * 16;
            uint32_t ch = (uint32_t)((ks * 2 + akp) ^ (r & 7));
            uint32_t off = r * 256 + (ch << 4);
            ldm_x4(ah[mt], sb + SMO_AH + off);
            ldm_x4(al[mt], sb + SMO_AL + off);
        }
#pragma unroll
        for (int np = 0; np < 4; np++) {
            int n = bn + np * 16;
            uint32_t ch = (uint32_t)((ks * 2 + bkp) ^ (n & 7));
            uint32_t off = n * 256 + (ch << 4);
            uint32_t bh[4], bl[4];
            ldm_x4(bh, sb + SMO_BH + off);
            ldm_x4(bl, sb + SMO_BL + off);
#pragma unroll
            for (int mt = 0; mt < 2; mt++) {
#pragma unroll
                for (int sn = 0; sn < 2; sn++) {
                    float* c = acc[mt][np * 2 + sn];
                    mma16816(c, ah[mt], bh + sn * 2);
                    mma16816(c, ah[mt], bl + sn * 2);
                    mma16816(c, al[mt], bh + sn * 2);
                }
            }
        }
    }

    const int g = lid >> 2;
    const int tig = lid & 3;
#pragma unroll
    for (int nt = 0; nt < 8; nt++) {
        int nl = wn * 64 + nt * 8 + 2 * tig;
        float b0 = bias_s[nl], b1 = bias_s[nl + 1];
        float s0 = 0.f, s1 = 0.f, q0 = 0.f, q1 = 0.f;
#pragma unroll
        for (int mt = 0; mt < 2; mt++) {
            int m = m0 + wm * 32 + mt * 16 + g;
            if (m < P.M) {
                float ox = acc[mt][nt][0] + b0, oy = acc[mt][nt][1] + b1;
                *reinterpret_cast<float2*>(P.C + (size_t)m * PD + nl) = make_float2(ox, oy);
                s0 += ox; s1 += oy; q0 += ox * ox; q1 += oy * oy;
            }
            if (m + 8 < P.M) {
                float ox = acc[mt][nt][2] + b0, oy = acc[mt][nt][3] + b1;
                *reinterpret_cast<float2*>(P.C + (size_t)(m + 8) * PD + nl) = make_float2(ox, oy);
                s0 += ox; s1 += oy; q0 += ox * ox; q1 += oy * oy;
            }
        }
#pragma unroll
        for (int d = 4; d < 32; d <<= 1) {
            s0 += __shfl_xor_sync(0xFFFFFFFFu, s0, d);
            s1 += __shfl_xor_sync(0xFFFFFFFFu, s1, d);
            q0 += __shfl_xor_sync(0xFFFFFFFFu, q0, d);
            q1 += __shfl_xor_sync(0xFFFFFFFFu, q1, d);
        }
        if (g == 0) {
            atomicAdd(P.stats + nl, s0);
            atomicAdd(P.stats + nl + 1, s1);
            atomicAdd(P.stats + PD + nl, q0);
            atomicAdd(P.stats + PD + nl + 1, q1);
        }
    }
}

// ---------------- fused SAGE + MERGE pair: cp.async-staged phase 1 ------------------
// smem: bias1 @0(1K), bias2 @1024(0.5K), scale @1536(1K), shift @2560(1K), cnt @3584(0.5K)
//   phase1: SPLIT @4096 (hi 16K, lo 16K), STAGE @36864 (32K fp32),
//           B1 @69632: 2 bufs x 64K (hi 32K + lo 32K)          -> ends 200704
//   phase2/3: A2 hi @69632 (64K), lo @135168 (64K);  B2 @4096: 2 x 32K
#define F_BIAS1 0
#define F_BIAS2 1024
#define F_SCALE 1536
#define F_SHIFT 2560
#define F_CNT   3584
#define F_SPLIT 4096
#define F_STAGE 36864
#define F_B1    69632
#define F_A2H   69632
#define F_A2L   135168
#define F_B2    4096
#define SMEM_FUSED 200704

struct FusedP {
    const float *aggm, *xdst, *cnt;
    const __nv_bfloat16 *b1h, *b1l;
    const float *sbl, *sbr, *pre;
    const float *stats, *gamma, *beta;
    const __nv_bfloat16 *b2h, *b2l;
    const float *mbias;
    float *C;
    int M;
    float invM;
};

__global__ __launch_bounds__(512)
void sage_merge_pair(FusedP Pa, FusedP Pc) {
    const bool isA = blockIdx.x < GAC;
    const FusedP P = isA ? Pa : Pc;
    const int m0 = (isA ? blockIdx.x : blockIdx.x - GAC) * 128;

    extern __shared__ char smem[];
    uint32_t sb = smem_u32(smem);
    const int tid = threadIdx.x;
    const int wid = tid >> 5;
    const int lid = tid & 31;

    float* bias1_s = reinterpret_cast<float*>(smem + F_BIAS1);
    float* bias2_s = reinterpret_cast<float*>(smem + F_BIAS2);
    float* scale_s = reinterpret_cast<float*>(smem + F_SCALE);
    float* shift_s = reinterpret_cast<float*>(smem + F_SHIFT);
    float* cnt_s   = reinterpret_cast<float*>(smem + F_CNT);
    if (tid < 256) {
        bias1_s[tid] = P.sbl[tid] + P.sbr[tid];
        // inline BN finalize
        float mu = P.stats[tid] * P.invM;
        float var = P.stats[PD + tid] * P.invM - mu * mu;
        float s = P.gamma[tid] * rsqrtf(var + BN_EPS);
        scale_s[tid] = s;
        shift_s[tid] = P.beta[tid] - mu * s;
    } else if (tid < 384) {
        bias2_s[tid - 256] = P.mbias[tid - 256];
    } else {
        int m = m0 + (tid - 384);
        cnt_s[tid - 384] = (m < P.M) ? __frcp_rn(fmaxf(P.cnt[m], 1.0f)) : 1.0f;
    }

    // ===== Phase 1: SAGE GEMM (K=256), 4 chunks of k=64, cp.async-staged A =====
    const int wm = wid & 3;
    const int wn = wid >> 2;
    float acc[2][8][4];
#pragma unroll
    for (int mt = 0; mt < 2; mt++)
#pragma unroll
        for (int nt = 0; nt < 8; nt++)
#pragma unroll
            for (int j = 0; j < 4; j++) acc[mt][nt][j] = 0.0f;

    const int arow = wm * 32 + (lid & 15);
    const int akp = lid >> 4;
    const int bn = wn * 64 + (lid & 7) + ((lid >> 4) << 3);
    const int bkp = (lid >> 3) & 1;

    auto loadB1 = [&](int c, int b) {
#pragma unroll
        for (int it = 0; it < 4; it++) {
            int idx = tid + it * 512;          // 0..2047
            int n = idx >> 3;
            int ch = idx & 7;
            uint32_t off = n * 128 + ((ch ^ (n & 7)) << 4);
            cp16(sb + F_B1 + b * 65536 + off, P.b1h + (size_t)n * 256 + c * 64 + ch * 8);
            cp16(sb + F_B1 + b * 65536 + 32768 + off, P.b1l + (size_t)n * 256 + c * 64 + ch * 8);
        }
    };
    auto loadStage = [&](int c) {
        const float* base = (c < 2) ? P.aggm : P.xdst;
        int koff = (c & 1) * 64;
#pragma unroll
        for (int it = 0; it < 4; it++) {
            int idx = tid + it * 512;          // 0..2047 float4 slots
            int r = idx >> 4;
            int gr = m0 + r;
            int c4 = (idx & 15) * 4;
            const float* src = (gr < P.M)
                ? base + (size_t)gr * 128 + koff + c4
                : base + koff + c4;            // safe fallback row 0
            cp16(sb + F_STAGE + idx * 16, src);
        }
    };
    auto transform = [&](int c) {
        float scale_row = 1.0f;  // placeholder; per-row below
#pragma unroll
        for (int it = 0; it < 4; it++) {
            int idx = tid + it * 512;
            int r = idx >> 4;
            int c4 = (idx & 15) * 4;
            int gr = m0 + r;
            float4 v = *reinterpret_cast<const float4*>(smem + F_STAGE + idx * 16);
            if (gr >= P.M) v = make_float4(0.f, 0.f, 0.f, 0.f);
            if (c < 2) {
                float inv = cnt_s[r];
                v.x *= inv; v.y *= inv; v.z *= inv; v.w *= inv;
            }
            uint2 hp, lp;
            split4(v, hp, lp);
            uint32_t off = r * 128 + (((c4 >> 3) ^ (r & 7)) << 4) + ((c4 & 4) << 1);
            *reinterpret_cast<uint2*>(smem + F_SPLIT + off) = hp;
            *reinterpret_cast<uint2*>(smem + F_SPLIT + 16384 + off) = lp;
        }
        (void)scale_row;
    };
    auto mma1 = [&](int b) {
        uint32_t abase = sb + F_SPLIT;
        uint32_t bbase = sb + F_B1 + b * 65536;
#pragma unroll
        for (int ks = 0; ks < 4; ks++) {
            uint32_t ah[2][4], al[2][4];
#pragma unroll
            for (int mt = 0; mt < 2; mt++) {
                int r = arow + mt * 16;
                uint32_t ch = (uint32_t)((ks * 2 + akp) ^ (r & 7));
                uint32_t off = r * 128 + (ch << 4);
                ldm_x4(ah[mt], abase + off);
                ldm_x4(al[mt], abase + 16384 + off);
            }
#pragma unroll
            for (int np = 0; np < 4; np++) {
                int n = bn + np * 16;
                uint32_t ch = (uint32_t)((ks * 2 + bkp) ^ (n & 7));
                uint32_t off = n * 128 + (ch << 4);
                uint32_t bh[4], blx[4];
                ldm_x4(bh, bbase + off);
                ldm_x4(blx, bbase + 32768 + off);
#pragma unroll
                for (int mt = 0; mt < 2; mt++) {
#pragma unroll
                    for (int sn = 0; sn < 2; sn++) {
                        float* c = acc[mt][np * 2 + sn];
                        mma16816(c, ah[mt], bh + sn * 2);
                        mma16816(c, ah[mt], blx + sn * 2);
                        mma16816(c, al[mt], bh + sn * 2);
                    }
                }
            }
        }
    };

    loadB1(0, 0);
    loadStage(0);
    CP_COMMIT();
#pragma unroll
    for (int c = 0; c < 4; c++) {
        CP_WAIT0();
        __syncthreads();            // stage(c)/B1(c) ready; split free (prev MMA done)
        transform(c);
        __syncthreads();            // split visible; stage free for reuse
        if (c < 3) {
            loadB1(c + 1, (c + 1) & 1);
            loadStage(c + 1);
            CP_COMMIT();            // these fly under MMA(c)
        }
        mma1(c & 1);
    }
    __syncthreads();                // all MMAs done before B2/A2 reuse regions

    // ===== B2 prefetch: chunks 0,1 of 4 (k=64) into freed split/stage region =====
    auto loadB2 = [&](int c, int b) {
#pragma unroll
        for (int it = 0; it < 2; it++) {
            int idx = tid + it * 512;          // 0..1023
            int n = idx >> 3;
            int ch = idx & 7;
            uint32_t off = n * 128 + ((ch ^ (n & 7)) << 4);
            cp16(sb + F_B2 + b * 32768 + off, P.b2h + (size_t)n * 256 + c * 64 + ch * 8);
            cp16(sb + F_B2 + b * 32768 + 16384 + off, P.b2l + (size_t)n * 256 + c * 64 + ch * 8);
        }
        CP_COMMIT();
    };
    loadB2(0, 0);
    loadB2(1, 1);

    // ===== Phase 2: A2 = relu(pre*scale+shift) + S + bias -> smem split bf16 =====
    {
        const int g = lid >> 2;
        const int tig = lid & 3;
#pragma unroll
        for (int nt = 0; nt < 8; nt++) {
            int nl = wn * 64 + nt * 8 + 2 * tig;
            float b0 = bias1_s[nl], b1 = bias1_s[nl + 1];
            float sc0 = scale_s[nl], sc1 = scale_s[nl + 1];
            float sh0 = shift_s[nl], sh1 = shift_s[nl + 1];
#pragma unroll
            for (int mt = 0; mt < 2; mt++) {
#pragma unroll
                for (int half = 0; half < 2; half++) {
                    int r = wm * 32 + mt * 16 + g + half * 8;
                    int m = m0 + r;
                    float ax = 0.f, ay = 0.f;
                    if (m < P.M) {
                        float2 p = *reinterpret_cast<const float2*>(P.pre + (size_t)m * PD + nl);
                        ax = fmaxf(fmaf(p.x, sc0, sh0), 0.f) + acc[mt][nt][half * 2 + 0] + b0;
                        ay = fmaxf(fmaf(p.y, sc1, sh1), 0.f) + acc[mt][nt][half * 2 + 1] + b1;
                    }
                    uint32_t bx = __float_as_uint(ax), by = __float_as_uint(ay);
                    uint32_t hp = __byte_perm(bx, by, 0x7632);
                    uint32_t lp = pack_lo_bf16(ax - __uint_as_float(bx & 0xFFFF0000u),
                                               ay - __uint_as_float(by & 0xFFFF0000u));
                    uint32_t off = r * 512 + (((nl >> 3) ^ (r & 7)) << 4) + (nl & 7) * 2;
                    *reinterpret_cast<uint32_t*>(smem + F_A2H + off) = hp;
                    *reinterpret_cast<uint32_t*>(smem + F_A2L + off) = lp;
                }
            }
        }
    }
    __syncthreads();

    // ===== Phase 3: merge GEMM from smem A2, 4 chunks k=64, double-buffered B2 =====
    const int wm2 = wid & 7;
    const int wn2 = wid >> 3;
    float acc2[8][4];
#pragma unroll
    for (int nt = 0; nt < 8; nt++)
#pragma unroll
        for (int j = 0; j < 4; j++) acc2[nt][j] = 0.0f;

    const int arow2 = wm2 * 16 + (lid & 15);
    const int akp2 = lid >> 4;
    const int bn2 = wn2 * 64 + (lid & 7) + ((lid >> 4) << 3);
    const int bkp2 = (lid >> 3) & 1;

    auto mma2 = [&](int c, int b) {
        uint32_t bbase = sb + F_B2 + b * 32768;
#pragma unroll
        for (int ks = 0; ks < 4; ks++) {
            uint32_t ah[4], al[4];
            {
                int r = arow2;
                uint32_t ch = (uint32_t)((c * 8 + ks * 2 + akp2) ^ (r & 7));
                uint32_t off = r * 512 + (ch << 4);
                ldm_x4(ah, sb + F_A2H + off);
                ldm_x4(al, sb + F_A2L + off);
            }
#pragma unroll
            for (int np = 0; np < 4; np++) {
                int n = bn2 + np * 16;
                uint32_t ch = (uint32_t)((ks * 2 + bkp2) ^ (n & 7));
                uint32_t off = n * 128 + (ch << 4);
                uint32_t bh[4], blx[4];
                ldm_x4(bh, bbase + off);
                ldm_x4(blx, bbase + 16384 + off);
#pragma unroll
                for (int sn = 0; sn < 2; sn++) {
                    float* cc = acc2[np * 2 + sn];
                    mma16816(cc, ah, bh + sn * 2);
                    mma16816(cc, ah, blx + sn * 2);
                    mma16816(cc, al, bh + sn * 2);
                }
            }
        }
    };

#pragma unroll
    for (int c = 0; c < 4; c++) {
        if (c == 3) CP_WAIT0(); else CP_WAIT1();
        __syncthreads();
        mma2(c, c & 1);
        __syncthreads();
        if (c < 2) loadB2(c + 2, c & 1);
    }

    // ===== epilogue =====
    {
        const int g = lid >> 2;
        const int tig = lid & 3;
#pragma unroll
        for (int nt = 0; nt < 8; nt++) {
            int nl = wn2 * 64 + nt * 8 + 2 * tig;
            float b0 = bias2_s[nl], b1 = bias2_s[nl + 1];
            int m = m0 + wm2 * 16 + g;
            if (m < P.M) {
                *reinterpret_cast<float2*>(P.C + (size_t)m * HD + nl) =
                    make_float2(acc2[nt][0] + b0, acc2[nt][1] + b1);
            }
            if (m + 8 < P.M) {
                *reinterpret_cast<float2*>(P.C + (size_t)(m + 8) * HD + nl) =
                    make_float2(acc2[nt][2] + b0, acc2[nt][3] + b1);
            }
        }
    }
}

// -----------------------------------------------------------------------------------
extern "C" void kernel_launch(void* const* d_in, const int* in_sizes, int n_in,
                              void* d_out, int out_size) {
    const float* x         = (const float*)d_in[0];
    const float* edge_attr = (const float*)d_in[1];
    const float* x_cl      = (const float*)d_in[2];
    const float* c2c_ea    = (const float*)d_in[3];

    int pbase, ebase;
    if (in_sizes[4] == 2 * EA) { ebase = 4; pbase = 8; }
    else                       { pbase = 4; ebase = 26; }

    const int* ei_a   = (const int*)d_in[ebase + 0];
    const int* ei_c2c = (const int*)d_in[ebase + 1];
    const int* ei_a2c = (const int*)d_in[ebase + 2];
    const int* ei_c2a = (const int*)d_in[ebase + 3];

    const float* atom_eps   = (const float*)d_in[pbase + 0];
    const float* atom_W     = (const float*)d_in[pbase + 1];
    const float* atom_b     = (const float*)d_in[pbase + 2];
    const float* atom_gamma = (const float*)d_in[pbase + 3];
    const float* atom_beta  = (const float*)d_in[pbase + 4];
    const float* cl_eps     = (const float*)d_in[pbase + 5];
    const float* cl_W       = (const float*)d_in[pbase + 6];
    const float* cl_b       = (const float*)d_in[pbase + 7];
    const float* cl_gamma   = (const float*)d_in[pbase + 8];
    const float* cl_beta    = (const float*)d_in[pbase + 9];
    const float* a2c_Wl     = (const float*)d_in[pbase + 10];
    const float* a2c_bl     = (const float*)d_in[pbase + 11];
    const float* a2c_Wr     = (const float*)d_in[pbase + 12];
    const float* a2c_br     = (const float*)d_in[pbase + 13];
    const float* c2a_Wl     = (const float*)d_in[pbase + 14];
    const float* c2a_bl     = (const float*)d_in[pbase + 15];
    const float* c2a_Wr     = (const float*)d_in[pbase + 16];
    const float* c2a_br     = (const float*)d_in[pbase + 17];
    const float* merge_atom_W = (const float*)d_in[pbase + 18];
    const float* merge_atom_b = (const float*)d_in[pbase + 19];
    const float* merge_cl_W   = (const float*)d_in[pbase + 20];
    const float* merge_cl_b   = (const float*)d_in[pbase + 21];

    float* out = (float*)d_out;

    float *p_zero, *p_pre_atom, *p_pre_cl;
    __nv_bfloat16 *p_Bt_hi, *p_Bt_lo;
    cudaGetSymbolAddress((void**)&p_zero, g_zero);
    cudaGetSymbolAddress((void**)&p_pre_atom, g_pre_atom);
    cudaGetSymbolAddress((void**)&p_pre_cl, g_pre_cl);
    cudaGetSymbolAddress((void**)&p_Bt_hi, g_Bt_hi);
    cudaGetSymbolAddress((void**)&p_Bt_lo, g_Bt_lo);

    float* p_agg_atom   = p_zero + Z_AGG_ATOM;
    float* p_agg_cl     = p_zero + Z_AGG_CL;
    float* p_aggm_c2a   = p_zero + Z_AGGM_C2A;
    float* p_aggm_a2c   = p_zero + Z_AGGM_A2C;
    float* p_cnt_c2a    = p_zero + Z_CNT_C2A;
    float* p_cnt_a2c    = p_zero + Z_CNT_A2C;
    float* p_stats_atom = p_zero + Z_STATS_A;
    float* p_stats_cl   = p_zero + Z_STATS_C;

    cudaMemsetAsync(p_zero, 0, (size_t)Z_TOTAL * 4, 0);

    cudaFuncSetAttribute((const void*)gine_gemm_pair,
                         cudaFuncAttributeMaxDynamicSharedMemorySize, SMEM_GINE);
    cudaFuncSetAttribute((const void*)sage_merge_pair,
                         cudaFuncAttributeMaxDynamicSharedMemorySize, SMEM_FUSED);

    // ---- mega scatter + wsplit ----
    {
        MegaArgs A;
        A.x = x; A.ea = edge_attr; A.xcl = x_cl; A.cea = c2c_ea;
        A.ei_a = ei_a; A.ei_c = ei_c2c; A.ei_a2c = ei_a2c; A.ei_c2a = ei_c2a;
        A.agg_atom = p_agg_atom; A.agg_cl = p_agg_cl;
        A.aggm_a2c = p_aggm_a2c; A.cnt_a2c = p_cnt_a2c;
        A.aggm_c2a = p_aggm_c2a; A.cnt_c2a = p_cnt_c2a;
        A.wsrc[0] = atom_W;  A.wsrc[1] = cl_W;
        A.wsrc[2] = c2a_Wl;  A.wsrc[3] = c2a_Wr;
        A.wsrc[4] = a2c_Wl;  A.wsrc[5] = a2c_Wr;
        A.wsrc[6] = merge_atom_W; A.wsrc[7] = merge_cl_W;
        A.oh = p_Bt_hi; A.ol = p_Bt_lo;
        mega_scatter<<<SCATTER_BLOCKS + WSPLIT_BLOCKS, 256>>>(A);
    }

    // ---- GINE GEMM pair ----
    {
        GineP Pa{x, p_agg_atom, p_Bt_hi + OFF_GA, p_Bt_lo + OFF_GA,
                 atom_b, atom_eps, p_stats_atom, p_pre_atom, NATOM};
        GineP Pc{x_cl, p_agg_cl, p_Bt_hi + OFF_GC, p_Bt_lo + OFF_GC,
                 cl_b, cl_eps, p_stats_cl, p_pre_cl, NCL};
        gine_gemm_pair<<<GAC + GCC, 512, SMEM_GINE>>>(Pa, Pc);
    }

    // ---- fused SAGE + MERGE pair (BN finalize inlined) ----
    {
        FusedP Pa{p_aggm_c2a, x, p_cnt_c2a,
                  p_Bt_hi + OFF_SA, p_Bt_lo + OFF_SA, c2a_bl, c2a_br,
                  p_pre_atom, p_stats_atom, atom_gamma, atom_beta,
                  p_Bt_hi + OFF_MA, p_Bt_lo + OFF_MA, merge_atom_b, out,
                  NATOM, 1.0f / NATOM};
        FusedP Pc{p_aggm_a2c, x_cl, p_cnt_a2c,
                  p_Bt_hi + OFF_SC, p_Bt_lo + OFF_SC, a2c_bl, a2c_br,
                  p_pre_cl, p_stats_cl, cl_gamma, cl_beta,
                  p_Bt_hi + OFF_MC, p_Bt_lo + OFF_MC, merge_cl_b,
                  out + (size_t)NATOM * HD,
                  NCL, 1.0f / NCL};
        sage_merge_pair<<<GAC + GCC, 512, SMEM_FUSED>>>(Pa, Pc);
    }
}

// round 16
// speedup vs baseline: 1.1571x; 1.0516x over previous
#include <cuda_runtime.h>
#include <cuda_bf16.h>
#include <cstdint>
#include <cstddef>

#define NATOM 100000
#define NCL   25000
#define EA    600000
#define EC    100000
#define EB    100000
#define HD    128
#define PD    256
#define BN_EPS 1e-5f
#define GAC   782
#define GCC   196

// ---------------- zeroed scratch arena (single memset) -----------------------------
#define Z_AGG_ATOM  0
#define Z_AGG_CL    12800000
#define Z_AGGM_C2A  16000000
#define Z_AGGM_A2C  28800000
#define Z_CNT_C2A   32000000
#define Z_CNT_A2C   32100000
#define Z_STATS_A   32125000
#define Z_STATS_C   32125512
#define Z_TOTAL     32126024
__device__ float g_zero[Z_TOTAL];

__device__ float g_pre_atom[(size_t)NATOM * PD];
__device__ float g_pre_cl[(size_t)NCL * PD];

#define OFF_GA 0
#define OFF_GC 32768
#define OFF_SA 65536
#define OFF_SC 131072
#define OFF_MA 196608
#define OFF_MC 229376
__device__ __nv_bfloat16 g_Bt_hi[262144];
__device__ __nv_bfloat16 g_Bt_lo[262144];

// ---------------- helpers ---------------------------------------------------------
__device__ __forceinline__ uint32_t smem_u32(const void* p) {
    uint32_t a;
    asm("{ .reg .u64 t; cvta.to.shared.u64 t, %1; cvt.u32.u64 %0, t; }" : "=r"(a) : "l"(p));
    return a;
}
__device__ __forceinline__ void ldm_x4(uint32_t* r, uint32_t addr) {
    asm volatile("ldmatrix.sync.aligned.m8n8.x4.shared.b16 {%0,%1,%2,%3}, [%4];"
                 : "=r"(r[0]), "=r"(r[1]), "=r"(r[2]), "=r"(r[3]) : "r"(addr));
}
__device__ __forceinline__ void mma16816(float* c, const uint32_t* a, const uint32_t* b) {
    asm volatile("mma.sync.aligned.m16n8k16.row.col.f32.bf16.bf16.f32 "
                 "{%0,%1,%2,%3}, {%4,%5,%6,%7}, {%8,%9}, {%0,%1,%2,%3};"
                 : "+f"(c[0]), "+f"(c[1]), "+f"(c[2]), "+f"(c[3])
                 : "r"(a[0]), "r"(a[1]), "r"(a[2]), "r"(a[3]), "r"(b[0]), "r"(b[1]));
}
__device__ __forceinline__ void red_v4(float* p, float a, float b, float c, float d) {
    asm volatile("red.global.add.v4.f32 [%0], {%1,%2,%3,%4};"
                 :: "l"(p), "f"(a), "f"(b), "f"(c), "f"(d) : "memory");
}
__device__ __forceinline__ void cp16(uint32_t s, const void* g) {
    asm volatile("cp.async.cg.shared.global [%0], [%1], 16;" :: "r"(s), "l"(g));
}
__device__ __forceinline__ uint32_t pack_lo_bf16(float lox, float loy) {
    uint32_t r;
    asm("cvt.rn.bf16x2.f32 %0, %1, %2;" : "=r"(r) : "f"(loy), "f"(lox));
    return r;
}
__device__ __forceinline__ float4 ldg_stream4(const float* p) {
    float4 v;
    uint64_t pol;
    asm("createpolicy.fractional.L2::evict_first.b64 %0, 1.0;" : "=l"(pol));
    asm("ld.global.nc.L2::cache_hint.v4.f32 {%0,%1,%2,%3}, [%4], %5;"
        : "=f"(v.x), "=f"(v.y), "=f"(v.z), "=f"(v.w) : "l"(p), "l"(pol));
    return v;
}
#define CP_COMMIT() asm volatile("cp.async.commit_group;" ::: "memory")
#define CP_WAIT0()  asm volatile("cp.async.wait_group 0;" ::: "memory")
#define CP_WAIT1()  asm volatile("cp.async.wait_group 1;" ::: "memory")

__device__ __forceinline__ void split4(float4 v, uint2& hp, uint2& lp) {
    uint32_t bx = __float_as_uint(v.x), by = __float_as_uint(v.y);
    uint32_t bz = __float_as_uint(v.z), bw = __float_as_uint(v.w);
    hp.x = __byte_perm(bx, by, 0x7632);
    hp.y = __byte_perm(bz, bw, 0x7632);
    lp.x = pack_lo_bf16(v.x - __uint_as_float(bx & 0xFFFF0000u),
                        v.y - __uint_as_float(by & 0xFFFF0000u));
    lp.y = pack_lo_bf16(v.z - __uint_as_float(bz & 0xFFFF0000u),
                        v.w - __uint_as_float(bw & 0xFFFF0000u));
}

// ---------------- mega scatter + wsplit (2 edges/warp, FIXED segmentation) ---------
__constant__ int c_ws_N[8]     = {256, 256, 256, 256, 256, 256, 128, 128};
__constant__ int c_ws_koff[8]  = {0, 0, 0, 128, 0, 128, 0, 0};
__constant__ int c_ws_kout[8]  = {128, 128, 256, 256, 256, 256, 256, 256};
__constant__ int c_ws_doff[8]  = {OFF_GA, OFF_GC, OFF_SA, OFF_SA, OFF_SC, OFF_SC, OFF_MA, OFF_MC};

struct MegaArgs {
    const float *x, *ea, *xcl, *cea;
    const int *ei_a, *ei_c, *ei_a2c, *ei_c2a;
    float *agg_atom, *agg_cl, *aggm_a2c, *cnt_a2c, *aggm_c2a, *cnt_c2a;
    const float* wsrc[8];
    __nv_bfloat16 *oh, *ol;
};

// warps: gine atom 300000 (600k edges) | gine cl 50000 (100k) |
//        sage a2c 50000 (100k)         | sage c2a 50000 (100k)  = 450000 warps
#define SCATTER_BLOCKS 56250
#define WSPLIT_BLOCKS  1024

__global__ void mega_scatter(MegaArgs A) {
    int b = blockIdx.x;
    if (b >= SCATTER_BLOCKS) {
        int i = (b - SCATTER_BLOCKS) * 256 + threadIdx.x;
        int seg = i >> 15;
        int w = i & 32767;
        int N = c_ws_N[seg];
        int k = w / N, n = w - k * N;
        float v = A.wsrc[seg][w];
        uint32_t bits = __float_as_uint(v);
        uint32_t hbits = bits & 0xFFFF0000u;
        float lo = v - __uint_as_float(hbits);
        size_t o = (size_t)n * c_ws_kout[seg] + c_ws_koff[seg] + k + c_ws_doff[seg];
        A.oh[o] = __ushort_as_bfloat16((unsigned short)(hbits >> 16));
        A.ol[o] = __float2bfloat16(lo);
        return;
    }
    int w = b * 8 + (threadIdx.x >> 5);
    int lane = threadIdx.x & 31;
    if (w < 300000) {
        // gine atom, 2 edges/warp
        int e0 = w * 2, e1 = e0 + 1;
        int s0 = A.ei_a[e0], s1 = A.ei_a[e1];
        int d0 = A.ei_a[EA + e0], d1 = A.ei_a[EA + e1];
        float4 x0 = reinterpret_cast<const float4*>(A.x + (size_t)s0 * HD)[lane];
        float4 x1 = reinterpret_cast<const float4*>(A.x + (size_t)s1 * HD)[lane];
        float4 e0v = ldg_stream4(A.ea + (size_t)e0 * HD + lane * 4);
        float4 e1v = ldg_stream4(A.ea + (size_t)e1 * HD + lane * 4);
        red_v4(A.agg_atom + (size_t)d0 * HD + lane * 4,
               fmaxf(x0.x + e0v.x, 0.0f), fmaxf(x0.y + e0v.y, 0.0f),
               fmaxf(x0.z + e0v.z, 0.0f), fmaxf(x0.w + e0v.w, 0.0f));
        red_v4(A.agg_atom + (size_t)d1 * HD + lane * 4,
               fmaxf(x1.x + e1v.x, 0.0f), fmaxf(x1.y + e1v.y, 0.0f),
               fmaxf(x1.z + e1v.z, 0.0f), fmaxf(x1.w + e1v.w, 0.0f));
    } else if (w < 350000) {
        // gine cluster, 2 edges/warp
        int e0 = (w - 300000) * 2, e1 = e0 + 1;
        int s0 = A.ei_c[e0], s1 = A.ei_c[e1];
        int d0 = A.ei_c[EC + e0], d1 = A.ei_c[EC + e1];
        float4 x0 = reinterpret_cast<const float4*>(A.xcl + (size_t)s0 * HD)[lane];
        float4 x1 = reinterpret_cast<const float4*>(A.xcl + (size_t)s1 * HD)[lane];
        float4 e0v = ldg_stream4(A.cea + (size_t)e0 * HD + lane * 4);
        float4 e1v = ldg_stream4(A.cea + (size_t)e1 * HD + lane * 4);
        red_v4(A.agg_cl + (size_t)d0 * HD + lane * 4,
               fmaxf(x0.x + e0v.x, 0.0f), fmaxf(x0.y + e0v.y, 0.0f),
               fmaxf(x0.z + e0v.z, 0.0f), fmaxf(x0.w + e0v.w, 0.0f));
        red_v4(A.agg_cl + (size_t)d1 * HD + lane * 4,
               fmaxf(x1.x + e1v.x, 0.0f), fmaxf(x1.y + e1v.y, 0.0f),
               fmaxf(x1.z + e1v.z, 0.0f), fmaxf(x1.w + e1v.w, 0.0f));
    } else if (w < 400000) {
        // sage atom2c, 2 edges/warp (full 100k edges)
        int e0 = (w - 350000) * 2, e1 = e0 + 1;
        int s0 = A.ei_a2c[e0], s1 = A.ei_a2c[e1];
        int d0 = A.ei_a2c[EB + e0], d1 = A.ei_a2c[EB + e1];
        float4 v0 = reinterpret_cast<const float4*>(A.x + (size_t)s0 * HD)[lane];
        float4 v1 = reinterpret_cast<const float4*>(A.x + (size_t)s1 * HD)[lane];
        red_v4(A.aggm_a2c + (size_t)d0 * HD + lane * 4, v0.x, v0.y, v0.z, v0.w);
        red_v4(A.aggm_a2c + (size_t)d1 * HD + lane * 4, v1.x, v1.y, v1.z, v1.w);
        if (lane == 0) {
            atomicAdd(&A.cnt_a2c[d0], 1.0f);
            atomicAdd(&A.cnt_a2c[d1], 1.0f);
        }
    } else {
        // sage c2atom, 2 edges/warp (full 100k edges)
        int e0 = (w - 400000) * 2, e1 = e0 + 1;
        int s0 = A.ei_c2a[e0], s1 = A.ei_c2a[e1];
        int d0 = A.ei_c2a[EB + e0], d1 = A.ei_c2a[EB + e1];
        float4 v0 = reinterpret_cast<const float4*>(A.xcl + (size_t)s0 * HD)[lane];
        float4 v1 = reinterpret_cast<const float4*>(A.xcl + (size_t)s1 * HD)[lane];
        red_v4(A.aggm_c2a + (size_t)d0 * HD + lane * 4, v0.x, v0.y, v0.z, v0.w);
        red_v4(A.aggm_c2a + (size_t)d1 * HD + lane * 4, v1.x, v1.y, v1.z, v1.w);
        if (lane == 0) {
            atomicAdd(&A.cnt_c2a[d0], 1.0f);
            atomicAdd(&A.cnt_c2a[d1], 1.0f);
        }
    }
}

// ---------------- GINE GEMM pair: cp.async-staged pipeline, 2 chunks of k=64 -------
#define G_BIAS  0
#define G_SPLIT 1024
#define G_STAGE 33792
#define G_B     99328
#define SMEM_GINE 230400

struct GineP {
    const float *A0, *A1;
    const __nv_bfloat16 *bh, *bl;
    const float *bias, *eps;
    float *stats, *C;
    int M;
};

__global__ __launch_bounds__(512)
void gine_gemm_pair(GineP Pa, GineP Pc) {
    const bool isA = blockIdx.x < GAC;
    const GineP P = isA ? Pa : Pc;
    const int m0 = (isA ? blockIdx.x : blockIdx.x - GAC) * 128;

    extern __shared__ char smem[];
    uint32_t sb = smem_u32(smem);
    const int tid = threadIdx.x;
    const int wid = tid >> 5;
    const int lid = tid & 31;
    const int wm = wid & 3;
    const int wn = wid >> 2;

    float* bias_s = reinterpret_cast<float*>(smem + G_BIAS);
    if (tid < 256) bias_s[tid] = P.bias[tid];

    const float ef = 1.0f + *P.eps;

    float acc[2][8][4];
#pragma unroll
    for (int mt = 0; mt < 2; mt++)
#pragma unroll
        for (int nt = 0; nt < 8; nt++)
#pragma unroll
            for (int j = 0; j < 4; j++) acc[mt][nt][j] = 0.0f;

    const int arow = wm * 32 + (lid & 15);
    const int akp = lid >> 4;
    const int bn = wn * 64 + (lid & 7) + ((lid >> 4) << 3);
    const int bkp = (lid >> 3) & 1;

    auto loadB = [&](int c, int b) {
#pragma unroll
        for (int it = 0; it < 4; it++) {
            int idx = tid + it * 512;
            int n = idx >> 3;
            int ch = idx & 7;
            uint32_t off = n * 128 + ((ch ^ (n & 7)) << 4);
            cp16(sb + G_B + b * 65536 + off, P.bh + (size_t)n * 128 + c * 64 + ch * 8);
            cp16(sb + G_B + b * 65536 + 32768 + off, P.bl + (size_t)n * 128 + c * 64 + ch * 8);
        }
    };
    auto loadStage = [&](int c) {
#pragma unroll
        for (int it = 0; it < 4; it++) {
            int idx = tid + it * 512;
            int r = idx >> 4;
            int gr = m0 + r;
            int c4 = (idx & 15) * 4;
            size_t rowoff = (gr < P.M) ? (size_t)gr * 128 : 0;
            cp16(sb + G_STAGE + idx * 16, P.A0 + rowoff + c * 64 + c4);
            cp16(sb + G_STAGE + 32768 + idx * 16, P.A1 + rowoff + c * 64 + c4);
        }
    };
    auto transform = [&](int /*c*/) {
#pragma unroll
        for (int it = 0; it < 4; it++) {
            int idx = tid + it * 512;
            int r = idx >> 4;
            int c4 = (idx & 15) * 4;
            int gr = m0 + r;
            float4 a = *reinterpret_cast<const float4*>(smem + G_STAGE + idx * 16);
            float4 g = *reinterpret_cast<const float4*>(smem + G_STAGE + 32768 + idx * 16);
            float4 v;
            v.x = fmaf(ef, a.x, g.x); v.y = fmaf(ef, a.y, g.y);
            v.z = fmaf(ef, a.z, g.z); v.w = fmaf(ef, a.w, g.w);
            if (gr >= P.M) v = make_float4(0.f, 0.f, 0.f, 0.f);
            uint2 hp, lp;
            split4(v, hp, lp);
            uint32_t off = r * 128 + (((c4 >> 3) ^ (r & 7)) << 4) + ((c4 & 4) << 1);
            *reinterpret_cast<uint2*>(smem + G_SPLIT + off) = hp;
            *reinterpret_cast<uint2*>(smem + G_SPLIT + 16384 + off) = lp;
        }
    };
    auto mma1 = [&](int b) {
        uint32_t abase = sb + G_SPLIT;
        uint32_t bbase = sb + G_B + b * 65536;
#pragma unroll
        for (int ks = 0; ks < 4; ks++) {
            uint32_t ah[2][4], al[2][4];
#pragma unroll
            for (int mt = 0; mt < 2; mt++) {
                int r = arow + mt * 16;
                uint32_t ch = (uint32_t)((ks * 2 + akp) ^ (r & 7));
                uint32_t off = r * 128 + (ch << 4);
                ldm_x4(ah[mt], abase + off);
                ldm_x4(al[mt], abase + 16384 + off);
            }
#pragma unroll
            for (int np = 0; np < 4; np++) {
                int n = bn + np * 16;
                uint32_t ch = (uint32_t)((ks * 2 + bkp) ^ (n & 7));
                uint32_t off = n * 128 + (ch << 4);
                uint32_t bh[4], bl[4];
                ldm_x4(bh, bbase + off);
                ldm_x4(bl, bbase + 32768 + off);
#pragma unroll
                for (int mt = 0; mt < 2; mt++) {
#pragma unroll
                    for (int sn = 0; sn < 2; sn++) {
                        float* c = acc[mt][np * 2 + sn];
                        mma16816(c, ah[mt], bh + sn * 2);
                        mma16816(c, ah[mt], bl + sn * 2);
                        mma16816(c, al[mt], bh + sn * 2);
                    }
                }
            }
        }
    };

    loadB(0, 0);
    loadStage(0);
    CP_COMMIT();
#pragma unroll
    for (int c = 0; c < 2; c++) {
        CP_WAIT0();
        __syncthreads();
        transform(c);
        __syncthreads();
        if (c < 1) {
            loadB(1, 1);
            loadStage(1);
            CP_COMMIT();
        }
        mma1(c & 1);
    }
    __syncthreads();

    // epilogue + fused column stats
    const int g = lid >> 2;
    const int tig = lid & 3;
#pragma unroll
    for (int nt = 0; nt < 8; nt++) {
        int nl = wn * 64 + nt * 8 + 2 * tig;
        float b0 = bias_s[nl], b1 = bias_s[nl + 1];
        float s0 = 0.f, s1 = 0.f, q0 = 0.f, q1 = 0.f;
#pragma unroll
        for (int mt = 0; mt < 2; mt++) {
            int m = m0 + wm * 32 + mt * 16 + g;
            if (m < P.M) {
                float ox = acc[mt][nt][0] + b0, oy = acc[mt][nt][1] + b1;
                *reinterpret_cast<float2*>(P.C + (size_t)m * PD + nl) = make_float2(ox, oy);
                s0 += ox; s1 += oy; q0 += ox * ox; q1 += oy * oy;
            }
            if (m + 8 < P.M) {
                float ox = acc[mt][nt][2] + b0, oy = acc[mt][nt][3] + b1;
                *reinterpret_cast<float2*>(P.C + (size_t)(m + 8) * PD + nl) = make_float2(ox, oy);
                s0 += ox; s1 += oy; q0 += ox * ox; q1 += oy * oy;
            }
        }
#pragma unroll
        for (int d = 4; d < 32; d <<= 1) {
            s0 += __shfl_xor_sync(0xFFFFFFFFu, s0, d);
            s1 += __shfl_xor_sync(0xFFFFFFFFu, s1, d);
            q0 += __shfl_xor_sync(0xFFFFFFFFu, q0, d);
            q1 += __shfl_xor_sync(0xFFFFFFFFu, q1, d);
        }
        if (g == 0) {
            atomicAdd(P.stats + nl, s0);
            atomicAdd(P.stats + nl + 1, s1);
            atomicAdd(P.stats + PD + nl, q0);
            atomicAdd(P.stats + PD + nl + 1, q1);
        }
    }
}

// ---------------- fused SAGE + MERGE pair (round-14, proven) ------------------------
#define F_BIAS1 0
#define F_BIAS2 1024
#define F_SCALE 1536
#define F_SHIFT 2560
#define F_CNT   3584
#define F_SPLIT 4096
#define F_STAGE 36864
#define F_B1    69632
#define F_A2H   69632
#define F_A2L   135168
#define F_B2    4096
#define SMEM_FUSED 200704

struct FusedP {
    const float *aggm, *xdst, *cnt;
    const __nv_bfloat16 *b1h, *b1l;
    const float *sbl, *sbr, *pre;
    const float *stats, *gamma, *beta;
    const __nv_bfloat16 *b2h, *b2l;
    const float *mbias;
    float *C;
    int M;
    float invM;
};

__global__ __launch_bounds__(512)
void sage_merge_pair(FusedP Pa, FusedP Pc) {
    const bool isA = blockIdx.x < GAC;
    const FusedP P = isA ? Pa : Pc;
    const int m0 = (isA ? blockIdx.x : blockIdx.x - GAC) * 128;

    extern __shared__ char smem[];
    uint32_t sb = smem_u32(smem);
    const int tid = threadIdx.x;
    const int wid = tid >> 5;
    const int lid = tid & 31;

    float* bias1_s = reinterpret_cast<float*>(smem + F_BIAS1);
    float* bias2_s = reinterpret_cast<float*>(smem + F_BIAS2);
    float* scale_s = reinterpret_cast<float*>(smem + F_SCALE);
    float* shift_s = reinterpret_cast<float*>(smem + F_SHIFT);
    float* cnt_s   = reinterpret_cast<float*>(smem + F_CNT);
    if (tid < 256) {
        bias1_s[tid] = P.sbl[tid] + P.sbr[tid];
        float mu = P.stats[tid] * P.invM;
        float var = P.stats[PD + tid] * P.invM - mu * mu;
        float s = P.gamma[tid] * rsqrtf(var + BN_EPS);
        scale_s[tid] = s;
        shift_s[tid] = P.beta[tid] - mu * s;
    } else if (tid < 384) {
        bias2_s[tid - 256] = P.mbias[tid - 256];
    } else {
        int m = m0 + (tid - 384);
        cnt_s[tid - 384] = (m < P.M) ? __frcp_rn(fmaxf(P.cnt[m], 1.0f)) : 1.0f;
    }

    const int wm = wid & 3;
    const int wn = wid >> 2;
    float acc[2][8][4];
#pragma unroll
    for (int mt = 0; mt < 2; mt++)
#pragma unroll
        for (int nt = 0; nt < 8; nt++)
#pragma unroll
            for (int j = 0; j < 4; j++) acc[mt][nt][j] = 0.0f;

    const int arow = wm * 32 + (lid & 15);
    const int akp = lid >> 4;
    const int bn = wn * 64 + (lid & 7) + ((lid >> 4) << 3);
    const int bkp = (lid >> 3) & 1;

    auto loadB1 = [&](int c, int b) {
#pragma unroll
        for (int it = 0; it < 4; it++) {
            int idx = tid + it * 512;
            int n = idx >> 3;
            int ch = idx & 7;
            uint32_t off = n * 128 + ((ch ^ (n & 7)) << 4);
            cp16(sb + F_B1 + b * 65536 + off, P.b1h + (size_t)n * 256 + c * 64 + ch * 8);
            cp16(sb + F_B1 + b * 65536 + 32768 + off, P.b1l + (size_t)n * 256 + c * 64 + ch * 8);
        }
    };
    auto loadStage = [&](int c) {
        const float* base = (c < 2) ? P.aggm : P.xdst;
        int koff = (c & 1) * 64;
#pragma unroll
        for (int it = 0; it < 4; it++) {
            int idx = tid + it * 512;
            int r = idx >> 4;
            int gr = m0 + r;
            int c4 = (idx & 15) * 4;
            const float* src = (gr < P.M)
                ? base + (size_t)gr * 128 + koff + c4
                : base + koff + c4;
            cp16(sb + F_STAGE + idx * 16, src);
        }
    };
    auto transform = [&](int c) {
#pragma unroll
        for (int it = 0; it < 4; it++) {
            int idx = tid + it * 512;
            int r = idx >> 4;
            int c4 = (idx & 15) * 4;
            int gr = m0 + r;
            float4 v = *reinterpret_cast<const float4*>(smem + F_STAGE + idx * 16);
            if (gr >= P.M) v = make_float4(0.f, 0.f, 0.f, 0.f);
            if (c < 2) {
                float inv = cnt_s[r];
                v.x *= inv; v.y *= inv; v.z *= inv; v.w *= inv;
            }
            uint2 hp, lp;
            split4(v, hp, lp);
            uint32_t off = r * 128 + (((c4 >> 3) ^ (r & 7)) << 4) + ((c4 & 4) << 1);
            *reinterpret_cast<uint2*>(smem + F_SPLIT + off) = hp;
            *reinterpret_cast<uint2*>(smem + F_SPLIT + 16384 + off) = lp;
        }
    };
    auto mma1 = [&](int b) {
        uint32_t abase = sb + F_SPLIT;
        uint32_t bbase = sb + F_B1 + b * 65536;
#pragma unroll
        for (int ks = 0; ks < 4; ks++) {
            uint32_t ah[2][4], al[2][4];
#pragma unroll
            for (int mt = 0; mt < 2; mt++) {
                int r = arow + mt * 16;
                uint32_t ch = (uint32_t)((ks * 2 + akp) ^ (r & 7));
                uint32_t off = r * 128 + (ch << 4);
                ldm_x4(ah[mt], abase + off);
                ldm_x4(al[mt], abase + 16384 + off);
            }
#pragma unroll
            for (int np = 0; np < 4; np++) {
                int n = bn + np * 16;
                uint32_t ch = (uint32_t)((ks * 2 + bkp) ^ (n & 7));
                uint32_t off = n * 128 + (ch << 4);
                uint32_t bh[4], blx[4];
                ldm_x4(bh, bbase + off);
                ldm_x4(blx, bbase + 32768 + off);
#pragma unroll
                for (int mt = 0; mt < 2; mt++) {
#pragma unroll
                    for (int sn = 0; sn < 2; sn++) {
                        float* c = acc[mt][np * 2 + sn];
                        mma16816(c, ah[mt], bh + sn * 2);
                        mma16816(c, ah[mt], blx + sn * 2);
                        mma16816(c, al[mt], bh + sn * 2);
                    }
                }
            }
        }
    };

    loadB1(0, 0);
    loadStage(0);
    CP_COMMIT();
#pragma unroll
    for (int c = 0; c < 4; c++) {
        CP_WAIT0();
        __syncthreads();
        transform(c);
        __syncthreads();
        if (c < 3) {
            loadB1(c + 1, (c + 1) & 1);
            loadStage(c + 1);
            CP_COMMIT();
        }
        mma1(c & 1);
    }
    __syncthreads();

    auto loadB2 = [&](int c, int b) {
#pragma unroll
        for (int it = 0; it < 2; it++) {
            int idx = tid + it * 512;
            int n = idx >> 3;
            int ch = idx & 7;
            uint32_t off = n * 128 + ((ch ^ (n & 7)) << 4);
            cp16(sb + F_B2 + b * 32768 + off, P.b2h + (size_t)n * 256 + c * 64 + ch * 8);
            cp16(sb + F_B2 + b * 32768 + 16384 + off, P.b2l + (size_t)n * 256 + c * 64 + ch * 8);
        }
        CP_COMMIT();
    };
    loadB2(0, 0);
    loadB2(1, 1);

    // Phase 2
    {
        const int g = lid >> 2;
        const int tig = lid & 3;
#pragma unroll
        for (int nt = 0; nt < 8; nt++) {
            int nl = wn * 64 + nt * 8 + 2 * tig;
            float b0 = bias1_s[nl], b1 = bias1_s[nl + 1];
            float sc0 = scale_s[nl], sc1 = scale_s[nl + 1];
            float sh0 = shift_s[nl], sh1 = shift_s[nl + 1];
#pragma unroll
            for (int mt = 0; mt < 2; mt++) {
#pragma unroll
                for (int half = 0; half < 2; half++) {
                    int r = wm * 32 + mt * 16 + g + half * 8;
                    int m = m0 + r;
                    float ax = 0.f, ay = 0.f;
                    if (m < P.M) {
                        float2 p = *reinterpret_cast<const float2*>(P.pre + (size_t)m * PD + nl);
                        ax = fmaxf(fmaf(p.x, sc0, sh0), 0.f) + acc[mt][nt][half * 2 + 0] + b0;
                        ay = fmaxf(fmaf(p.y, sc1, sh1), 0.f) + acc[mt][nt][half * 2 + 1] + b1;
                    }
                    uint32_t bx = __float_as_uint(ax), by = __float_as_uint(ay);
                    uint32_t hp = __byte_perm(bx, by, 0x7632);
                    uint32_t lp = pack_lo_bf16(ax - __uint_as_float(bx & 0xFFFF0000u),
                                               ay - __uint_as_float(by & 0xFFFF0000u));
                    uint32_t off = r * 512 + (((nl >> 3) ^ (r & 7)) << 4) + (nl & 7) * 2;
                    *reinterpret_cast<uint32_t*>(smem + F_A2H + off) = hp;
                    *reinterpret_cast<uint32_t*>(smem + F_A2L + off) = lp;
                }
            }
        }
    }
    __syncthreads();

    // Phase 3
    const int wm2 = wid & 7;
    const int wn2 = wid >> 3;
    float acc2[8][4];
#pragma unroll
    for (int nt = 0; nt < 8; nt++)
#pragma unroll
        for (int j = 0; j < 4; j++) acc2[nt][j] = 0.0f;

    const int arow2 = wm2 * 16 + (lid & 15);
    const int akp2 = lid >> 4;
    const int bn2 = wn2 * 64 + (lid & 7) + ((lid >> 4) << 3);
    const int bkp2 = (lid >> 3) & 1;

    auto mma2 = [&](int c, int b) {
        uint32_t bbase = sb + F_B2 + b * 32768;
#pragma unroll
        for (int ks = 0; ks < 4; ks++) {
            uint32_t ah[4], al[4];
            {
                int r = arow2;
                uint32_t ch = (uint32_t)((c * 8 + ks * 2 + akp2) ^ (r & 7));
                uint32_t off = r * 512 + (ch << 4);
                ldm_x4(ah, sb + F_A2H + off);
                ldm_x4(al, sb + F_A2L + off);
            }
#pragma unroll
            for (int np = 0; np < 4; np++) {
                int n = bn2 + np * 16;
                uint32_t ch = (uint32_t)((ks * 2 + bkp2) ^ (n & 7));
                uint32_t off = n * 128 + (ch << 4);
                uint32_t bh[4], blx[4];
                ldm_x4(bh, bbase + off);
                ldm_x4(blx, bbase + 16384 + off);
#pragma unroll
                for (int sn = 0; sn < 2; sn++) {
                    float* cc = acc2[np * 2 + sn];
                    mma16816(cc, ah, bh + sn * 2);
                    mma16816(cc, ah, blx + sn * 2);
                    mma16816(cc, al, bh + sn * 2);
                }
            }
        }
    };

#pragma unroll
    for (int c = 0; c < 4; c++) {
        if (c == 3) CP_WAIT0(); else CP_WAIT1();
        __syncthreads();
        mma2(c, c & 1);
        __syncthreads();
        if (c < 2) loadB2(c + 2, c & 1);
    }

    // epilogue
    {
        const int g = lid >> 2;
        const int tig = lid & 3;
#pragma unroll
        for (int nt = 0; nt < 8; nt++) {
            int nl = wn2 * 64 + nt * 8 + 2 * tig;
            float b0 = bias2_s[nl], b1 = bias2_s[nl + 1];
            int m = m0 + wm2 * 16 + g;
            if (m < P.M) {
                *reinterpret_cast<float2*>(P.C + (size_t)m * HD + nl) =
                    make_float2(acc2[nt][0] + b0, acc2[nt][1] + b1);
            }
            if (m + 8 < P.M) {
                *reinterpret_cast<float2*>(P.C + (size_t)(m + 8) * HD + nl) =
                    make_float2(acc2[nt][2] + b0, acc2[nt][3] + b1);
            }
        }
    }
}

// -----------------------------------------------------------------------------------
extern "C" void kernel_launch(void* const* d_in, const int* in_sizes, int n_in,
                              void* d_out, int out_size) {
    const float* x         = (const float*)d_in[0];
    const float* edge_attr = (const float*)d_in[1];
    const float* x_cl      = (const float*)d_in[2];
    const float* c2c_ea    = (const float*)d_in[3];

    int pbase, ebase;
    if (in_sizes[4] == 2 * EA) { ebase = 4; pbase = 8; }
    else                       { pbase = 4; ebase = 26; }

    const int* ei_a   = (const int*)d_in[ebase + 0];
    const int* ei_c2c = (const int*)d_in[ebase + 1];
    const int* ei_a2c = (const int*)d_in[ebase + 2];
    const int* ei_c2a = (const int*)d_in[ebase + 3];

    const float* atom_eps   = (const float*)d_in[pbase + 0];
    const float* atom_W     = (const float*)d_in[pbase + 1];
    const float* atom_b     = (const float*)d_in[pbase + 2];
    const float* atom_gamma = (const float*)d_in[pbase + 3];
    const float* atom_beta  = (const float*)d_in[pbase + 4];
    const float* cl_eps     = (const float*)d_in[pbase + 5];
    const float* cl_W       = (const float*)d_in[pbase + 6];
    const float* cl_b       = (const float*)d_in[pbase + 7];
    const float* cl_gamma   = (const float*)d_in[pbase + 8];
    const float* cl_beta    = (const float*)d_in[pbase + 9];
    const float* a2c_Wl     = (const float*)d_in[pbase + 10];
    const float* a2c_bl     = (const float*)d_in[pbase + 11];
    const float* a2c_Wr     = (const float*)d_in[pbase + 12];
    const float* a2c_br     = (const float*)d_in[pbase + 13];
    const float* c2a_Wl     = (const float*)d_in[pbase + 14];
    const float* c2a_bl     = (const float*)d_in[pbase + 15];
    const float* c2a_Wr     = (const float*)d_in[pbase + 16];
    const float* c2a_br     = (const float*)d_in[pbase + 17];
    const float* merge_atom_W = (const float*)d_in[pbase + 18];
    const float* merge_atom_b = (const float*)d_in[pbase + 19];
    const float* merge_cl_W   = (const float*)d_in[pbase + 20];
    const float* merge_cl_b   = (const float*)d_in[pbase + 21];

    float* out = (float*)d_out;

    float *p_zero, *p_pre_atom, *p_pre_cl;
    __nv_bfloat16 *p_Bt_hi, *p_Bt_lo;
    cudaGetSymbolAddress((void**)&p_zero, g_zero);
    cudaGetSymbolAddress((void**)&p_pre_atom, g_pre_atom);
    cudaGetSymbolAddress((void**)&p_pre_cl, g_pre_cl);
    cudaGetSymbolAddress((void**)&p_Bt_hi, g_Bt_hi);
    cudaGetSymbolAddress((void**)&p_Bt_lo, g_Bt_lo);

    float* p_agg_atom   = p_zero + Z_AGG_ATOM;
    float* p_agg_cl     = p_zero + Z_AGG_CL;
    float* p_aggm_c2a   = p_zero + Z_AGGM_C2A;
    float* p_aggm_a2c   = p_zero + Z_AGGM_A2C;
    float* p_cnt_c2a    = p_zero + Z_CNT_C2A;
    float* p_cnt_a2c    = p_zero + Z_CNT_A2C;
    float* p_stats_atom = p_zero + Z_STATS_A;
    float* p_stats_cl   = p_zero + Z_STATS_C;

    cudaMemsetAsync(p_zero, 0, (size_t)Z_TOTAL * 4, 0);

    cudaFuncSetAttribute((const void*)gine_gemm_pair,
                         cudaFuncAttributeMaxDynamicSharedMemorySize, SMEM_GINE);
    cudaFuncSetAttribute((const void*)sage_merge_pair,
                         cudaFuncAttributeMaxDynamicSharedMemorySize, SMEM_FUSED);

    // ---- mega scatter + wsplit ----
    {
        MegaArgs A;
        A.x = x; A.ea = edge_attr; A.xcl = x_cl; A.cea = c2c_ea;
        A.ei_a = ei_a; A.ei_c = ei_c2c; A.ei_a2c = ei_a2c; A.ei_c2a = ei_c2a;
        A.agg_atom = p_agg_atom; A.agg_cl = p_agg_cl;
        A.aggm_a2c = p_aggm_a2c; A.cnt_a2c = p_cnt_a2c;
        A.aggm_c2a = p_aggm_c2a; A.cnt_c2a = p_cnt_c2a;
        A.wsrc[0] = atom_W;  A.wsrc[1] = cl_W;
        A.wsrc[2] = c2a_Wl;  A.wsrc[3] = c2a_Wr;
        A.wsrc[4] = a2c_Wl;  A.wsrc[5] = a2c_Wr;
        A.wsrc[6] = merge_atom_W; A.wsrc[7] = merge_cl_W;
        A.oh = p_Bt_hi; A.ol = p_Bt_lo;
        mega_scatter<<<SCATTER_BLOCKS + WSPLIT_BLOCKS, 256>>>(A);
    }

    // ---- GINE GEMM pair (staged pipeline) ----
    {
        GineP Pa{x, p_agg_atom, p_Bt_hi + OFF_GA, p_Bt_lo + OFF_GA,
                 atom_b, atom_eps, p_stats_atom, p_pre_atom, NATOM};
        GineP Pc{x_cl, p_agg_cl, p_Bt_hi + OFF_GC, p_Bt_lo + OFF_GC,
                 cl_b, cl_eps, p_stats_cl, p_pre_cl, NCL};
        gine_gemm_pair<<<GAC + GCC, 512, SMEM_GINE>>>(Pa, Pc);
    }

    // ---- fused SAGE + MERGE pair (BN finalize inlined) ----
    {
        FusedP Pa{p_aggm_c2a, x, p_cnt_c2a,
                  p_Bt_hi + OFF_SA, p_Bt_lo + OFF_SA, c2a_bl, c2a_br,
                  p_pre_atom, p_stats_atom, atom_gamma, atom_beta,
                  p_Bt_hi + OFF_MA, p_Bt_lo + OFF_MA, merge_atom_b, out,
                  NATOM, 1.0f / NATOM};
        FusedP Pc{p_aggm_a2c, x_cl, p_cnt_a2c,
                  p_Bt_hi + OFF_SC, p_Bt_lo + OFF_SC, a2c_bl, a2c_br,
                  p_pre_cl, p_stats_cl, cl_gamma, cl_beta,
                  p_Bt_hi + OFF_MC, p_Bt_lo + OFF_MC, merge_cl_b,
                  out + (size_t)NATOM * HD,
                  NCL, 1.0f / NCL};
        sage_merge_pair<<<GAC + GCC, 512, SMEM_FUSED>>>(Pa, Pc);
    }
}